// round 12
// baseline (speedup 1.0000x reference)
#include <cuda_runtime.h>
#include <cuda_bf16.h>
#include <math.h>
#include <stdint.h>

#define BATCH 64
#define NMAX  2048
#define NEDGE 32768
#define FIN   256
#define NHID  512
#define RULES 128

// ---------------- scratch (device globals; no allocations) ----------------
static __device__ float g_bufA[(size_t)BATCH * NMAX * NHID];   // gemm outputs (ping)
static __device__ float g_bufB[(size_t)BATCH * NMAX * NHID];   // gemm outputs (pong)
static __device__ __align__(16) __nv_bfloat16 g_ahi[(size_t)BATCH * NMAX * NHID / 2];
static __device__ __align__(16) __nv_bfloat16 g_alo[(size_t)BATCH * NMAX * NHID / 2];
static __device__ __align__(16) __nv_bfloat16 g_whi[3][NHID * NHID];
static __device__ __align__(16) __nv_bfloat16 g_wlo[3][NHID * NHID];
static __device__ int   g_cnt[BATCH * NMAX];
static __device__ int   g_rowstart[BATCH * NMAX];
static __device__ int   g_csr[BATCH * NEDGE];
static __device__ int2  g_sinfo[BATCH * NMAX];   // (old-space row, bitcast(coef incl tv))
static __device__ float g_s0[BATCH * NMAX];
static __device__ float g_tv[BATCH * NMAX];
static __device__ int   g_perm[BATCH * NMAX];
static __device__ int   g_newidx[BATCH * NMAX];
static __device__ int   g_src[BATCH * NEDGE];
static __device__ int   g_dst[BATCH * NEDGE];
static __device__ float g_em[BATCH * NEDGE];
static __device__ float g_z[BATCH * 2 * NHID];

// ---------------- helpers ----------------
__device__ __forceinline__ uint32_t smem_u32(const void* p) {
    uint32_t a;
    asm("{ .reg .u64 t; cvta.to.shared.u64 t, %1; cvt.u32.u64 %0, t; }" : "=r"(a) : "l"(p));
    return a;
}
__device__ __forceinline__ void cp16(uint32_t saddr, const void* gptr) {
    asm volatile("cp.async.cg.shared.global [%0], [%1], 16;"
                 :: "r"(saddr), "l"(__cvta_generic_to_global(gptr)) : "memory");
}
__device__ __forceinline__ void ldsm4(uint32_t& r0, uint32_t& r1, uint32_t& r2, uint32_t& r3,
                                      uint32_t addr) {
    asm volatile("ldmatrix.sync.aligned.m8n8.x4.shared.b16 {%0,%1,%2,%3}, [%4];"
                 : "=r"(r0), "=r"(r1), "=r"(r2), "=r"(r3) : "r"(addr));
}
__device__ __forceinline__ void mma_bf16(float* c, uint32_t a0, uint32_t a1, uint32_t a2,
                                         uint32_t a3, uint32_t b0, uint32_t b1) {
    asm volatile(
        "mma.sync.aligned.m16n8k16.row.col.f32.bf16.bf16.f32 "
        "{%0,%1,%2,%3}, {%4,%5,%6,%7}, {%8,%9}, {%0,%1,%2,%3};"
        : "+f"(c[0]), "+f"(c[1]), "+f"(c[2]), "+f"(c[3])
        : "r"(a0), "r"(a1), "r"(a2), "r"(a3), "r"(b0), "r"(b1));
}
__device__ __forceinline__ uint32_t pk2(float a, float b) {
    __nv_bfloat162 t = __floats2bfloat162_rn(a, b);
    return *(uint32_t*)&t;
}

// ---------------- init ----------------
__global__ void k_zero_cnt(int total) {
    int i = blockIdx.x * blockDim.x + threadIdx.x;
    if (i < total) g_cnt[i] = 0;
}
__global__ void k_init_edges_count(const int* __restrict__ src, const int* __restrict__ dst) {
    int i = blockIdx.x * blockDim.x + threadIdx.x;
    if (i >= BATCH * NEDGE) return;
    int s = src[i], d = dst[i];
    g_src[i] = s; g_dst[i] = d; g_em[i] = 1.0f;
    int b = i / NEDGE;
    atomicAdd(&g_cnt[b * NMAX + d], 1);
}

// ---------------- fused per-batch scan + CSR fill + s0 zero + sinfo build ----------------
// n_old == 0 -> stage 1 (identity indirection)
__global__ __launch_bounds__(1024) void k_scan_fill(int n, int n_old) {
    __shared__ int buf[2][NMAX];
    __shared__ int cur[NMAX];
    int b = blockIdx.x, tid = threadIdx.x;
    for (int i = tid; i < n; i += 1024) buf[0][i] = g_cnt[b * n + i];
    __syncthreads();
    int s = 0;
    for (int d = 1; d < n; d <<= 1) {
        for (int i = tid; i < n; i += 1024) {
            int v = buf[s][i];
            if (i >= d) v += buf[s][i - d];
            buf[s ^ 1][i] = v;
        }
        __syncthreads();
        s ^= 1;
    }
    for (int i = tid; i < n; i += 1024) {
        int excl = (i == 0) ? 0 : buf[s][i - 1];
        g_rowstart[b * n + i] = excl;
        cur[i] = excl;
        g_s0[b * n + i] = 0.0f;
        int ci = g_cnt[b * n + i];
        float c = rsqrtf((float)(ci + 1));
        int2 si;
        if (n_old) {
            int p = g_perm[b * n_old + i];
            int old = b * n_old + p;
            si.x = old;
            si.y = __float_as_int(g_tv[old] * c);
        } else {
            si.x = b * n + i;
            si.y = __float_as_int(c);
        }
        g_sinfo[b * n + i] = si;
    }
    __syncthreads();
    for (int e = tid; e < NEDGE; e += 1024) {
        int i = b * NEDGE + e;
        if (g_em[i] != 0.0f) {
            int pos = atomicAdd(&cur[g_dst[i]], 1);
            g_csr[b * NEDGE + pos] = g_src[i];
        }
    }
}

// ---------------- warp-per-row GCN aggregation + bf16 split ----------------
// per-edge work: 1x LDG.64 sinfo + shfl; VEC float4 loads per lane per edge.
template<int VEC>
__global__ __launch_bounds__(256) void k_gather_w(const float* __restrict__ xin,
                                                  __nv_bfloat16* __restrict__ hi,
                                                  __nv_bfloat16* __restrict__ lo,
                                                  int n) {
    const int K = VEC * 128;
    const int gw = (blockIdx.x * 256 + threadIdx.x) >> 5;
    const int lane = threadIdx.x & 31;
    const int b = gw / n;
    const int bn = b * n;
    const int start = g_rowstart[gw];
    const int cnt = g_cnt[gw];
    const float dinv = rsqrtf((float)(cnt + 1));
    const int2 sself = g_sinfo[gw];

    float4 acc[VEC];
#pragma unroll
    for (int j = 0; j < VEC; j++) acc[j] = make_float4(0.f, 0.f, 0.f, 0.f);

    for (int base = 0; base < cnt; base += 32) {
        int m = min(32, cnt - base);
        int off = 0; float c = 0.0f;
        if (lane < m) {
            int s = g_csr[b * NEDGE + start + base + lane];
            int2 si = g_sinfo[bn + s];
            off = si.x * K;
            c = __int_as_float(si.y);
        }
#pragma unroll 8
        for (int e = 0; e < m; e++) {
            int o = __shfl_sync(0xffffffffu, off, e);
            float cc = __shfl_sync(0xffffffffu, c, e);
            const float4* p = (const float4*)(xin + o);
#pragma unroll
            for (int j = 0; j < VEC; j++) {
                float4 v = p[lane + j * 32];
                acc[j].x = fmaf(v.x, cc, acc[j].x);
                acc[j].y = fmaf(v.y, cc, acc[j].y);
                acc[j].z = fmaf(v.z, cc, acc[j].z);
                acc[j].w = fmaf(v.w, cc, acc[j].w);
            }
        }
    }
    const float scoef = __int_as_float(sself.y);
    const float4* selfp = (const float4*)(xin + (size_t)sself.x * K);
    uint2* hp = (uint2*)(hi + (size_t)gw * K);
    uint2* lp = (uint2*)(lo + (size_t)gw * K);
#pragma unroll
    for (int j = 0; j < VEC; j++) {
        float4 sv = selfp[lane + j * 32];
        float rx = dinv * fmaf(sv.x, scoef, acc[j].x);
        float ry = dinv * fmaf(sv.y, scoef, acc[j].y);
        float rz = dinv * fmaf(sv.z, scoef, acc[j].z);
        float rw = dinv * fmaf(sv.w, scoef, acc[j].w);
        float lx = rx - __bfloat162float(__float2bfloat16(rx));
        float ly = ry - __bfloat162float(__float2bfloat16(ry));
        float lz = rz - __bfloat162float(__float2bfloat16(rz));
        float lw = rw - __bfloat162float(__float2bfloat16(rw));
        hp[lane + j * 32] = make_uint2(pk2(rx, ry), pk2(rz, rw));
        lp[lane + j * 32] = make_uint2(pk2(lx, ly), pk2(lz, lw));
    }
}

// ---------------- weight split + transpose via smem tile ----------------
__global__ void k_split_w(const float* __restrict__ W, __nv_bfloat16* __restrict__ hi,
                          __nv_bfloat16* __restrict__ lo, int K) {
    __shared__ float tile[32][33];
    const int k0 = blockIdx.x * 32, n0 = blockIdx.y * 32;
    const int tx = threadIdx.x, ty = threadIdx.y;
#pragma unroll
    for (int j = 0; j < 4; j++) {
        int kr = ty + j * 8;
        tile[kr][tx] = W[(size_t)(k0 + kr) * 512 + n0 + tx];
    }
    __syncthreads();
#pragma unroll
    for (int j = 0; j < 4; j++) {
        int nr = ty + j * 8;
        float v = tile[tx][nr];
        __nv_bfloat16 h = __float2bfloat16(v);
        size_t o = (size_t)(n0 + nr) * K + k0 + tx;
        hi[o] = h;
        lo[o] = __float2bfloat16(v - __bfloat162float(h));
    }
}

// ---------------- split-bf16 tensor GEMM + fused bias/relu/scorer epilogue ----------------
#define LDS_E   40
#define TILE_A  (128 * LDS_E * 2)
#define TILE_BS (256 * LDS_E * 2)
#define STAGE_B (2 * TILE_A + 2 * TILE_BS)
#define GEMM_SMEM (3 * STAGE_B)
__global__ __launch_bounds__(512, 1) void k_gemm_mma(
    const __nv_bfloat16* __restrict__ Ahi, const __nv_bfloat16* __restrict__ Alo,
    const __nv_bfloat16* __restrict__ Bhi, const __nv_bfloat16* __restrict__ Blo,
    float* __restrict__ C, const float* __restrict__ bias, const float* __restrict__ Wp,
    int M, int K)
{
    extern __shared__ __align__(128) char smem[];
    const uint32_t sb = smem_u32(smem);
    const int tid = threadIdx.x;
    const int wid = tid >> 5;
    const int lane = tid & 31;
    const int warp_m = wid & 3;
    const int warp_n = wid >> 2;
    const int rowBase = blockIdx.y * 128;
    const int colBase = blockIdx.x * 256;

    const int g = lane >> 3;
    const int a_m = lane & 15;
    const int a_k = (lane >> 4) << 3;
    const int b_n = lane - ((g == 0) ? 0 : (g == 3) ? 16 : 8);
    const int b_k = (g & 1) << 3;

    uint32_t aoff[2], boff[4];
#pragma unroll
    for (int mt = 0; mt < 2; mt++)
        aoff[mt] = ((warp_m * 32 + mt * 16 + a_m) * LDS_E + a_k) * 2;
#pragma unroll
    for (int ng = 0; ng < 4; ng++)
        boff[ng] = ((warp_n * 64 + ng * 16 + b_n) * LDS_E + b_k) * 2;

    float acc[2][8][4];
#pragma unroll
    for (int mt = 0; mt < 2; mt++)
#pragma unroll
        for (int nf = 0; nf < 8; nf++)
#pragma unroll
            for (int e = 0; e < 4; e++) acc[mt][nf][e] = 0.0f;

    const int nch = K >> 5;

    auto load_stage = [&](int t) {
        const uint32_t base = sb + (t % 3) * STAGE_B;
        const int kc0 = t << 5;
        {
            int r = tid >> 2, blk = tid & 3;
            uint32_t so = r * (LDS_E * 2) + blk * 16;
            size_t ga = (size_t)(rowBase + r) * K + kc0 + blk * 8;
            cp16(base + so,          Ahi + ga);
            cp16(base + TILE_A + so, Alo + ga);
        }
#pragma unroll
        for (int part = 0; part < 2; part++) {
            int idx = tid + part * 512;
            int r = idx >> 2, blk = idx & 3;
            uint32_t so = r * (LDS_E * 2) + blk * 16;
            size_t gb = (size_t)(colBase + r) * K + kc0 + blk * 8;
            cp16(base + 2 * TILE_A + so,           Bhi + gb);
            cp16(base + 2 * TILE_A + TILE_BS + so, Blo + gb);
        }
        asm volatile("cp.async.commit_group;" ::: "memory");
    };

    load_stage(0);
    if (nch > 1) load_stage(1);
    for (int t = 0; t < nch; t++) {
        if (t + 2 < nch) {
            load_stage(t + 2);
            asm volatile("cp.async.wait_group 2;" ::: "memory");
        } else if (t + 1 < nch) {
            asm volatile("cp.async.wait_group 1;" ::: "memory");
        } else {
            asm volatile("cp.async.wait_group 0;" ::: "memory");
        }
        __syncthreads();
        const uint32_t base = sb + (t % 3) * STAGE_B;
        const uint32_t bbase = base + 2 * TILE_A;
#pragma unroll
        for (int kk = 0; kk < 2; kk++) {
            const uint32_t ko = kk * 32;
            uint32_t ah[2][4], al[2][4];
#pragma unroll
            for (int mt = 0; mt < 2; mt++) {
                ldsm4(ah[mt][0], ah[mt][1], ah[mt][2], ah[mt][3], base + aoff[mt] + ko);
                ldsm4(al[mt][0], al[mt][1], al[mt][2], al[mt][3], base + TILE_A + aoff[mt] + ko);
            }
#pragma unroll
            for (int half = 0; half < 2; half++) {
                uint32_t bh[4][2], bl[4][2];
#pragma unroll
                for (int gg = 0; gg < 2; gg++) {
                    int ng = half * 2 + gg;
                    uint32_t r0, r1, r2, r3;
                    ldsm4(r0, r1, r2, r3, bbase + boff[ng] + ko);
                    bh[gg * 2][0] = r0; bh[gg * 2][1] = r1;
                    bh[gg * 2 + 1][0] = r2; bh[gg * 2 + 1][1] = r3;
                    ldsm4(r0, r1, r2, r3, bbase + TILE_BS + boff[ng] + ko);
                    bl[gg * 2][0] = r0; bl[gg * 2][1] = r1;
                    bl[gg * 2 + 1][0] = r2; bl[gg * 2 + 1][1] = r3;
                }
#pragma unroll
                for (int mt = 0; mt < 2; mt++)
#pragma unroll
                    for (int q = 0; q < 4; q++) {
                        int nf = half * 4 + q;
                        mma_bf16(acc[mt][nf], ah[mt][0], ah[mt][1], ah[mt][2], ah[mt][3],
                                 bh[q][0], bh[q][1]);
                        mma_bf16(acc[mt][nf], ah[mt][0], ah[mt][1], ah[mt][2], ah[mt][3],
                                 bl[q][0], bl[q][1]);
                        mma_bf16(acc[mt][nf], al[mt][0], al[mt][1], al[mt][2], al[mt][3],
                                 bh[q][0], bh[q][1]);
                    }
            }
        }
        __syncthreads();
    }

    float sdot[2][2] = {{0.f, 0.f}, {0.f, 0.f}};
#pragma unroll
    for (int mt = 0; mt < 2; mt++) {
        int r0 = rowBase + warp_m * 32 + mt * 16 + (lane >> 2);
        int r1 = r0 + 8;
#pragma unroll
        for (int nf = 0; nf < 8; nf++) {
            int col = colBase + warp_n * 64 + nf * 8 + (lane & 3) * 2;
            float b0 = bias[col], b1 = bias[col + 1];
            float w0 = Wp[col],   w1 = Wp[col + 1];
            float v00 = fmaxf(acc[mt][nf][0] + b0, 0.0f);
            float v01 = fmaxf(acc[mt][nf][1] + b1, 0.0f);
            float v10 = fmaxf(acc[mt][nf][2] + b0, 0.0f);
            float v11 = fmaxf(acc[mt][nf][3] + b1, 0.0f);
            *(float2*)(C + (size_t)r0 * 512 + col) = make_float2(v00, v01);
            *(float2*)(C + (size_t)r1 * 512 + col) = make_float2(v10, v11);
            sdot[mt][0] = fmaf(v00, w0, fmaf(v01, w1, sdot[mt][0]));
            sdot[mt][1] = fmaf(v10, w0, fmaf(v11, w1, sdot[mt][1]));
        }
    }
#pragma unroll
    for (int off = 1; off < 4; off <<= 1) {
#pragma unroll
        for (int mt = 0; mt < 2; mt++) {
            sdot[mt][0] += __shfl_xor_sync(0xffffffffu, sdot[mt][0], off);
            sdot[mt][1] += __shfl_xor_sync(0xffffffffu, sdot[mt][1], off);
        }
    }
    if ((lane & 3) == 0) {
#pragma unroll
        for (int mt = 0; mt < 2; mt++) {
            int r0 = rowBase + warp_m * 32 + mt * 16 + (lane >> 2);
            atomicAdd(&g_s0[r0], sdot[mt][0]);
            atomicAdd(&g_s0[r0 + 8], sdot[mt][1]);
        }
    }
}

// ---------------- fused score + top-k (+ tv store, next-stage cnt zero) ----------------
__global__ void k_topk(int n, int k, int kzero, const float* __restrict__ bp) {
    extern __shared__ char sm[];
    float* sv = (float*)sm;
    int* si = (int*)(sv + n);
    int b = blockIdx.x, tid = threadIdx.x;
    const float bias = bp[0];
    for (int i = tid; i < n; i += blockDim.x) {
        int c = g_cnt[b * n + i];
        sv[i] = g_s0[b * n + i] / (float)(c + 1) + bias;
        si[i] = i;
    }
    __syncthreads();
    for (int e = tid; e < NEDGE; e += blockDim.x) {
        int i = b * NEDGE + e;
        if (g_em[i] != 0.0f) {
            int s = g_src[i], d = g_dst[i];
            float cs = rsqrtf((float)(g_cnt[b * n + s] + 1));
            float cd = rsqrtf((float)(g_cnt[b * n + d] + 1));
            atomicAdd(&sv[d], g_s0[b * n + s] * cs * cd);
        }
    }
    __syncthreads();
    for (int ksz = 2; ksz <= n; ksz <<= 1) {
        for (int j = ksz >> 1; j > 0; j >>= 1) {
            for (int i = tid; i < n; i += blockDim.x) {
                int ixj = i ^ j;
                if (ixj > i) {
                    float v1 = sv[i], v2 = sv[ixj];
                    int i1 = si[i], i2 = si[ixj];
                    bool before = (v1 > v2) || (v1 == v2 && i1 < i2);
                    bool desc = ((i & ksz) == 0);
                    if (desc ? !before : before) {
                        sv[i] = v2; sv[ixj] = v1; si[i] = i2; si[ixj] = i1;
                    }
                }
            }
            __syncthreads();
        }
    }
    for (int i = tid; i < n; i += blockDim.x) g_newidx[b * n + i] = -1;
    __syncthreads();
    for (int t = tid; t < k; t += blockDim.x) {
        int p = si[t];
        g_perm[b * n + t] = p;
        g_newidx[b * n + p] = t;
        g_tv[b * n + p] = tanhf(sv[t]);
    }
    if (kzero) {
        for (int j = tid; j < kzero; j += blockDim.x) g_cnt[b * kzero + j] = 0;
    }
}

// ---------------- readout (max/mean over selected rows) ----------------
__global__ __launch_bounds__(128) void k_pool_readout(const float* __restrict__ h,
                                                      int n, int k, int first) {
    __shared__ float tv[1024];
    __shared__ int   pp[1024];
    const int b = blockIdx.x, fc = blockIdx.y, t = threadIdx.x;
    for (int r = t; r < k; r += 128) {
        int p = g_perm[b * n + r];
        pp[r] = p;
        tv[r] = g_tv[b * n + p];
    }
    __syncthreads();
    const int f = fc * 128 + t;
    float mx = -INFINITY, sm = 0.0f;
    for (int r = 0; r < k; r++) {
        float v = h[((size_t)b * n + pp[r]) * NHID + f] * tv[r];
        mx = fmaxf(mx, v);
        sm += v;
    }
    if (first) {
        g_z[b * 1024 + f] = mx;
        g_z[b * 1024 + 512 + f] = sm / (float)k;
    } else {
        g_z[b * 1024 + f] += mx;
        g_z[b * 1024 + 512 + f] += sm / (float)k;
    }
}

// ---------------- edge relabel + count for next stage ----------------
__global__ void k_edge_update_count(int n, int k) {
    int i = blockIdx.x * blockDim.x + threadIdx.x;
    if (i >= BATCH * NEDGE) return;
    int b = i / NEDGE;
    if (g_em[i] != 0.0f) {
        int ns = g_newidx[b * n + g_src[i]];
        int nd = g_newidx[b * n + g_dst[i]];
        if (ns >= 0 && nd >= 0) {
            g_src[i] = ns; g_dst[i] = nd;
            atomicAdd(&g_cnt[b * k + nd], 1);
        } else { g_em[i] = 0.0f; g_src[i] = 0; g_dst[i] = 0; }
    } else { g_src[i] = 0; g_dst[i] = 0; }
}

// ---------------- head ----------------
__global__ void k_head(const float* __restrict__ l1W, const float* __restrict__ l1b,
                       const float* __restrict__ l2W, const float* __restrict__ l2b,
                       const float* __restrict__ piW, const float* __restrict__ pib,
                       const float* __restrict__ vW, const float* __restrict__ vb,
                       float* __restrict__ out) {
    __shared__ float zz[1024];
    __shared__ float z1[512];
    __shared__ float z2[256];
    __shared__ float lg[128];
    __shared__ float stats[2];
    int b = blockIdx.x, tid = threadIdx.x;
    for (int i = tid; i < 1024; i += 256) zz[i] = g_z[b * 1024 + i];
    __syncthreads();
    for (int j = tid; j < 512; j += 256) {
        float a = l1b[j];
        for (int i = 0; i < 1024; i++) a = fmaf(zz[i], l1W[i * 512 + j], a);
        z1[j] = fmaxf(a, 0.0f);
    }
    __syncthreads();
    {
        int j = tid;
        float a = l2b[j];
        for (int i = 0; i < 512; i++) a = fmaf(z1[i], l2W[i * 256 + j], a);
        z2[j] = fmaxf(a, 0.0f);
    }
    __syncthreads();
    if (tid < 128) {
        float a = pib[tid];
        for (int i = 0; i < 256; i++) a = fmaf(z2[i], piW[i * 128 + tid], a);
        lg[tid] = a;
    } else if (tid == 128) {
        float a = vb[0];
        for (int i = 0; i < 256; i++) a = fmaf(z2[i], vW[i], a);
        out[BATCH * RULES + b] = fmaxf(a, 0.0f);
    }
    __syncthreads();
    if (tid == 0) {
        float mx = -INFINITY;
        for (int i = 0; i < 128; i++) mx = fmaxf(mx, lg[i]);
        float s = 0.0f;
        for (int i = 0; i < 128; i++) s += expf(lg[i] - mx);
        stats[0] = mx;
        stats[1] = logf(s);
    }
    __syncthreads();
    if (tid < 128) out[b * RULES + tid] = lg[tid] - stats[0] - stats[1];
}

// ---------------- host orchestration ----------------
extern "C" void kernel_launch(void* const* d_in, const int* in_sizes, int n_in,
                              void* d_out, int out_size) {
    const float* x    = (const float*)d_in[0];
    const int*   src  = (const int*)d_in[1];
    const int*   dst  = (const int*)d_in[2];
    const float* W1   = (const float*)d_in[3];
    const float* b1   = (const float*)d_in[4];
    const float* Wp1  = (const float*)d_in[5];
    const float* bp1  = (const float*)d_in[6];
    const float* W2   = (const float*)d_in[7];
    const float* b2   = (const float*)d_in[8];
    const float* Wp2  = (const float*)d_in[9];
    const float* bp2  = (const float*)d_in[10];
    const float* W3   = (const float*)d_in[11];
    const float* b3   = (const float*)d_in[12];
    const float* Wp3  = (const float*)d_in[13];
    const float* bp3  = (const float*)d_in[14];
    const float* l1W  = (const float*)d_in[15];
    const float* l1b  = (const float*)d_in[16];
    const float* l2W  = (const float*)d_in[17];
    const float* l2b  = (const float*)d_in[18];
    const float* piW  = (const float*)d_in[19];
    const float* pib  = (const float*)d_in[20];
    const float* vW   = (const float*)d_in[21];
    const float* vb   = (const float*)d_in[22];
    float* out = (float*)d_out;

    float *pA = nullptr, *pB = nullptr;
    __nv_bfloat16 *ahi = nullptr, *alo = nullptr;
    __nv_bfloat16 (*whi)[NHID * NHID] = nullptr, (*wlo)[NHID * NHID] = nullptr;
    cudaGetSymbolAddress((void**)&pA, g_bufA);
    cudaGetSymbolAddress((void**)&pB, g_bufB);
    cudaGetSymbolAddress((void**)&ahi, g_ahi);
    cudaGetSymbolAddress((void**)&alo, g_alo);
    cudaGetSymbolAddress((void**)&whi, g_whi);
    cudaGetSymbolAddress((void**)&wlo, g_wlo);

    cudaFuncSetAttribute(k_gemm_mma, cudaFuncAttributeMaxDynamicSharedMemorySize, GEMM_SMEM);

    const int EB = BATCH * NEDGE;

    k_zero_cnt<<<(BATCH * NMAX + 255) / 256, 256>>>(BATCH * NMAX);
    k_init_edges_count<<<(EB + 255) / 256, 256>>>(src, dst);
    // all weight splits off the critical path
    k_split_w<<<dim3(FIN / 32, 16),  dim3(32, 8)>>>(W1, whi[0], wlo[0], FIN);
    k_split_w<<<dim3(NHID / 32, 16), dim3(32, 8)>>>(W2, whi[1], wlo[1], NHID);
    k_split_w<<<dim3(NHID / 32, 16), dim3(32, 8)>>>(W3, whi[2], wlo[2], NHID);

    // ---- stage 1: n=2048, K=256 ----
    k_scan_fill<<<BATCH, 1024>>>(2048, 0);
    k_gather_w<2><<<BATCH * 2048 / 8, 256>>>(x, ahi, alo, 2048);
    k_gemm_mma<<<dim3(2, BATCH * 2048 / 128), 512, GEMM_SMEM>>>(
        ahi, alo, whi[0], wlo[0], pA, b1, Wp1, BATCH * 2048, FIN);
    k_topk<<<BATCH, 1024, 2048 * 8>>>(2048, 1024, 1024, bp1);
    k_pool_readout<<<dim3(BATCH, 4), 128>>>(pA, 2048, 1024, 1);
    k_edge_update_count<<<(EB + 255) / 256, 256>>>(2048, 1024);

    // ---- stage 2: n=1024, K=512 ----
    k_scan_fill<<<BATCH, 1024>>>(1024, 2048);
    k_gather_w<4><<<BATCH * 1024 / 8, 256>>>(pA, ahi, alo, 1024);
    k_gemm_mma<<<dim3(2, BATCH * 1024 / 128), 512, GEMM_SMEM>>>(
        ahi, alo, whi[1], wlo[1], pB, b2, Wp2, BATCH * 1024, NHID);
    k_topk<<<BATCH, 1024, 1024 * 8>>>(1024, 512, 512, bp2);
    k_pool_readout<<<dim3(BATCH, 4), 128>>>(pB, 1024, 512, 0);
    k_edge_update_count<<<(EB + 255) / 256, 256>>>(1024, 512);

    // ---- stage 3: n=512, K=512 ----
    k_scan_fill<<<BATCH, 1024>>>(512, 1024);
    k_gather_w<4><<<BATCH * 512 / 8, 256>>>(pB, ahi, alo, 512);
    k_gemm_mma<<<dim3(2, BATCH * 512 / 128), 512, GEMM_SMEM>>>(
        ahi, alo, whi[2], wlo[2], pA, b3, Wp3, BATCH * 512, NHID);
    k_topk<<<BATCH, 1024, 512 * 8>>>(512, 256, 0, bp3);
    k_pool_readout<<<dim3(BATCH, 4), 128>>>(pA, 512, 256, 0);

    k_head<<<BATCH, 256>>>(l1W, l1b, l2W, l2b, piW, pib, vW, vb, out);
}

// round 13
// speedup vs baseline: 1.0054x; 1.0054x over previous
#include <cuda_runtime.h>
#include <cuda_bf16.h>
#include <math.h>
#include <stdint.h>

#define BATCH 64
#define NMAX  2048
#define NEDGE 32768
#define FIN   256
#define NHID  512
#define RULES 128

// ---------------- scratch (device globals; no allocations) ----------------
static __device__ float g_bufA[(size_t)BATCH * NMAX * NHID];   // gemm outputs (ping)
static __device__ float g_bufB[(size_t)BATCH * NMAX * NHID];   // gemm outputs (pong)
static __device__ __align__(16) __nv_bfloat16 g_ahi[(size_t)BATCH * NMAX * NHID / 2];
static __device__ __align__(16) __nv_bfloat16 g_alo[(size_t)BATCH * NMAX * NHID / 2];
static __device__ __align__(16) __nv_bfloat16 g_whi[3][NHID * NHID];
static __device__ __align__(16) __nv_bfloat16 g_wlo[3][NHID * NHID];
static __device__ int   g_cnt[BATCH * NMAX];
static __device__ int   g_rowstart[BATCH * NMAX];
static __device__ int   g_csr[BATCH * NEDGE];
static __device__ int2  g_sinfo[BATCH * NMAX];   // (old-space row, bitcast(coef incl tv))
static __device__ float g_s0[BATCH * NMAX];
static __device__ float g_score[BATCH * NMAX];
static __device__ float g_tv[BATCH * NMAX];
static __device__ int   g_perm[BATCH * NMAX];
static __device__ int   g_newidx[BATCH * NMAX];
static __device__ int   g_src[BATCH * NEDGE];
static __device__ int   g_dst[BATCH * NEDGE];
static __device__ float g_em[BATCH * NEDGE];
static __device__ float g_z[BATCH * 2 * NHID];

// ---------------- helpers ----------------
__device__ __forceinline__ uint32_t smem_u32(const void* p) {
    uint32_t a;
    asm("{ .reg .u64 t; cvta.to.shared.u64 t, %1; cvt.u32.u64 %0, t; }" : "=r"(a) : "l"(p));
    return a;
}
__device__ __forceinline__ void cp16(uint32_t saddr, const void* gptr) {
    asm volatile("cp.async.cg.shared.global [%0], [%1], 16;"
                 :: "r"(saddr), "l"(__cvta_generic_to_global(gptr)) : "memory");
}
__device__ __forceinline__ void ldsm4(uint32_t& r0, uint32_t& r1, uint32_t& r2, uint32_t& r3,
                                      uint32_t addr) {
    asm volatile("ldmatrix.sync.aligned.m8n8.x4.shared.b16 {%0,%1,%2,%3}, [%4];"
                 : "=r"(r0), "=r"(r1), "=r"(r2), "=r"(r3) : "r"(addr));
}
__device__ __forceinline__ void mma_bf16(float* c, uint32_t a0, uint32_t a1, uint32_t a2,
                                         uint32_t a3, uint32_t b0, uint32_t b1) {
    asm volatile(
        "mma.sync.aligned.m16n8k16.row.col.f32.bf16.bf16.f32 "
        "{%0,%1,%2,%3}, {%4,%5,%6,%7}, {%8,%9}, {%0,%1,%2,%3};"
        : "+f"(c[0]), "+f"(c[1]), "+f"(c[2]), "+f"(c[3])
        : "r"(a0), "r"(a1), "r"(a2), "r"(a3), "r"(b0), "r"(b1));
}
__device__ __forceinline__ uint32_t pk2(float a, float b) {
    __nv_bfloat162 t = __floats2bfloat162_rn(a, b);
    return *(uint32_t*)&t;
}

// ---------------- init ----------------
__global__ void k_zero_cnt(int total) {
    int i = blockIdx.x * blockDim.x + threadIdx.x;
    if (i < total) g_cnt[i] = 0;
}
__global__ void k_init_edges_count(const int* __restrict__ src, const int* __restrict__ dst) {
    int i = blockIdx.x * blockDim.x + threadIdx.x;
    if (i >= BATCH * NEDGE) return;
    int s = src[i], d = dst[i];
    g_src[i] = s; g_dst[i] = d; g_em[i] = 1.0f;
    int b = i / NEDGE;
    atomicAdd(&g_cnt[b * NMAX + d], 1);
}

// ---------------- fused per-batch scan + CSR fill + s0 zero + sinfo build ----------------
// n_old == 0 -> stage 1 (identity indirection)
__global__ __launch_bounds__(1024) void k_scan_fill(int n, int n_old) {
    __shared__ int buf[2][NMAX];
    __shared__ int cur[NMAX];
    int b = blockIdx.x, tid = threadIdx.x;
    for (int i = tid; i < n; i += 1024) buf[0][i] = g_cnt[b * n + i];
    __syncthreads();
    int s = 0;
    for (int d = 1; d < n; d <<= 1) {
        for (int i = tid; i < n; i += 1024) {
            int v = buf[s][i];
            if (i >= d) v += buf[s][i - d];
            buf[s ^ 1][i] = v;
        }
        __syncthreads();
        s ^= 1;
    }
    for (int i = tid; i < n; i += 1024) {
        int excl = (i == 0) ? 0 : buf[s][i - 1];
        g_rowstart[b * n + i] = excl;
        cur[i] = excl;
        g_s0[b * n + i] = 0.0f;
        int ci = g_cnt[b * n + i];
        float c = rsqrtf((float)(ci + 1));
        int2 si;
        if (n_old) {
            int p = g_perm[b * n_old + i];
            int old = b * n_old + p;
            si.x = old;
            si.y = __float_as_int(g_tv[old] * c);
        } else {
            si.x = b * n + i;
            si.y = __float_as_int(c);
        }
        g_sinfo[b * n + i] = si;
    }
    __syncthreads();
    for (int e = tid; e < NEDGE; e += 1024) {
        int i = b * NEDGE + e;
        if (g_em[i] != 0.0f) {
            int pos = atomicAdd(&cur[g_dst[i]], 1);
            g_csr[b * NEDGE + pos] = g_src[i];
        }
    }
}

// ---------------- warp-per-row GCN aggregation + bf16 split ----------------
template<int VEC>
__global__ __launch_bounds__(256) void k_gather_w(const float* __restrict__ xin,
                                                  __nv_bfloat16* __restrict__ hi,
                                                  __nv_bfloat16* __restrict__ lo,
                                                  int n) {
    const int K = VEC * 128;
    const int gw = (blockIdx.x * 256 + threadIdx.x) >> 5;
    const int lane = threadIdx.x & 31;
    const int b = gw / n;
    const int bn = b * n;
    const int start = g_rowstart[gw];
    const int cnt = g_cnt[gw];
    const float dinv = rsqrtf((float)(cnt + 1));
    const int2 sself = g_sinfo[gw];

    float4 acc[VEC];
#pragma unroll
    for (int j = 0; j < VEC; j++) acc[j] = make_float4(0.f, 0.f, 0.f, 0.f);

    for (int base = 0; base < cnt; base += 32) {
        int m = min(32, cnt - base);
        int off = 0; float c = 0.0f;
        if (lane < m) {
            int s = g_csr[b * NEDGE + start + base + lane];
            int2 si = g_sinfo[bn + s];
            off = si.x * K;
            c = __int_as_float(si.y);
        }
#pragma unroll 8
        for (int e = 0; e < m; e++) {
            int o = __shfl_sync(0xffffffffu, off, e);
            float cc = __shfl_sync(0xffffffffu, c, e);
            const float4* p = (const float4*)(xin + o);
#pragma unroll
            for (int j = 0; j < VEC; j++) {
                float4 v = p[lane + j * 32];
                acc[j].x = fmaf(v.x, cc, acc[j].x);
                acc[j].y = fmaf(v.y, cc, acc[j].y);
                acc[j].z = fmaf(v.z, cc, acc[j].z);
                acc[j].w = fmaf(v.w, cc, acc[j].w);
            }
        }
    }
    const float scoef = __int_as_float(sself.y);
    const float4* selfp = (const float4*)(xin + (size_t)sself.x * K);
    uint2* hp = (uint2*)(hi + (size_t)gw * K);
    uint2* lp = (uint2*)(lo + (size_t)gw * K);
#pragma unroll
    for (int j = 0; j < VEC; j++) {
        float4 sv = selfp[lane + j * 32];
        float rx = dinv * fmaf(sv.x, scoef, acc[j].x);
        float ry = dinv * fmaf(sv.y, scoef, acc[j].y);
        float rz = dinv * fmaf(sv.z, scoef, acc[j].z);
        float rw = dinv * fmaf(sv.w, scoef, acc[j].w);
        float lx = rx - __bfloat162float(__float2bfloat16(rx));
        float ly = ry - __bfloat162float(__float2bfloat16(ry));
        float lz = rz - __bfloat162float(__float2bfloat16(rz));
        float lw = rw - __bfloat162float(__float2bfloat16(rw));
        hp[lane + j * 32] = make_uint2(pk2(rx, ry), pk2(rz, rw));
        lp[lane + j * 32] = make_uint2(pk2(lx, ly), pk2(lz, lw));
    }
}

// ---------------- weight split + transpose via smem tile ----------------
__global__ void k_split_w(const float* __restrict__ W, __nv_bfloat16* __restrict__ hi,
                          __nv_bfloat16* __restrict__ lo, int K) {
    __shared__ float tile[32][33];
    const int k0 = blockIdx.x * 32, n0 = blockIdx.y * 32;
    const int tx = threadIdx.x, ty = threadIdx.y;
#pragma unroll
    for (int j = 0; j < 4; j++) {
        int kr = ty + j * 8;
        tile[kr][tx] = W[(size_t)(k0 + kr) * 512 + n0 + tx];
    }
    __syncthreads();
#pragma unroll
    for (int j = 0; j < 4; j++) {
        int nr = ty + j * 8;
        float v = tile[tx][nr];
        __nv_bfloat16 h = __float2bfloat16(v);
        size_t o = (size_t)(n0 + nr) * K + k0 + tx;
        hi[o] = h;
        lo[o] = __float2bfloat16(v - __bfloat162float(h));
    }
}

// ---------------- split-bf16 tensor GEMM + fused bias/relu/scorer epilogue ----------------
#define LDS_E   40
#define TILE_A  (128 * LDS_E * 2)
#define TILE_BS (256 * LDS_E * 2)
#define STAGE_B (2 * TILE_A + 2 * TILE_BS)
#define GEMM_SMEM (3 * STAGE_B)
__global__ __launch_bounds__(512, 1) void k_gemm_mma(
    const __nv_bfloat16* __restrict__ Ahi, const __nv_bfloat16* __restrict__ Alo,
    const __nv_bfloat16* __restrict__ Bhi, const __nv_bfloat16* __restrict__ Blo,
    float* __restrict__ C, const float* __restrict__ bias, const float* __restrict__ Wp,
    int M, int K)
{
    extern __shared__ __align__(128) char smem[];
    const uint32_t sb = smem_u32(smem);
    const int tid = threadIdx.x;
    const int wid = tid >> 5;
    const int lane = tid & 31;
    const int warp_m = wid & 3;
    const int warp_n = wid >> 2;
    const int rowBase = blockIdx.y * 128;
    const int colBase = blockIdx.x * 256;

    const int g = lane >> 3;
    const int a_m = lane & 15;
    const int a_k = (lane >> 4) << 3;
    const int b_n = lane - ((g == 0) ? 0 : (g == 3) ? 16 : 8);
    const int b_k = (g & 1) << 3;

    uint32_t aoff[2], boff[4];
#pragma unroll
    for (int mt = 0; mt < 2; mt++)
        aoff[mt] = ((warp_m * 32 + mt * 16 + a_m) * LDS_E + a_k) * 2;
#pragma unroll
    for (int ng = 0; ng < 4; ng++)
        boff[ng] = ((warp_n * 64 + ng * 16 + b_n) * LDS_E + b_k) * 2;

    float acc[2][8][4];
#pragma unroll
    for (int mt = 0; mt < 2; mt++)
#pragma unroll
        for (int nf = 0; nf < 8; nf++)
#pragma unroll
            for (int e = 0; e < 4; e++) acc[mt][nf][e] = 0.0f;

    const int nch = K >> 5;

    auto load_stage = [&](int t) {
        const uint32_t base = sb + (t % 3) * STAGE_B;
        const int kc0 = t << 5;
        {
            int r = tid >> 2, blk = tid & 3;
            uint32_t so = r * (LDS_E * 2) + blk * 16;
            size_t ga = (size_t)(rowBase + r) * K + kc0 + blk * 8;
            cp16(base + so,          Ahi + ga);
            cp16(base + TILE_A + so, Alo + ga);
        }
#pragma unroll
        for (int part = 0; part < 2; part++) {
            int idx = tid + part * 512;
            int r = idx >> 2, blk = idx & 3;
            uint32_t so = r * (LDS_E * 2) + blk * 16;
            size_t gb = (size_t)(colBase + r) * K + kc0 + blk * 8;
            cp16(base + 2 * TILE_A + so,           Bhi + gb);
            cp16(base + 2 * TILE_A + TILE_BS + so, Blo + gb);
        }
        asm volatile("cp.async.commit_group;" ::: "memory");
    };

    load_stage(0);
    if (nch > 1) load_stage(1);
    for (int t = 0; t < nch; t++) {
        if (t + 2 < nch) {
            load_stage(t + 2);
            asm volatile("cp.async.wait_group 2;" ::: "memory");
        } else if (t + 1 < nch) {
            asm volatile("cp.async.wait_group 1;" ::: "memory");
        } else {
            asm volatile("cp.async.wait_group 0;" ::: "memory");
        }
        __syncthreads();
        const uint32_t base = sb + (t % 3) * STAGE_B;
        const uint32_t bbase = base + 2 * TILE_A;
#pragma unroll
        for (int kk = 0; kk < 2; kk++) {
            const uint32_t ko = kk * 32;
            uint32_t ah[2][4], al[2][4];
#pragma unroll
            for (int mt = 0; mt < 2; mt++) {
                ldsm4(ah[mt][0], ah[mt][1], ah[mt][2], ah[mt][3], base + aoff[mt] + ko);
                ldsm4(al[mt][0], al[mt][1], al[mt][2], al[mt][3], base + TILE_A + aoff[mt] + ko);
            }
#pragma unroll
            for (int half = 0; half < 2; half++) {
                uint32_t bh[4][2], bl[4][2];
#pragma unroll
                for (int gg = 0; gg < 2; gg++) {
                    int ng = half * 2 + gg;
                    uint32_t r0, r1, r2, r3;
                    ldsm4(r0, r1, r2, r3, bbase + boff[ng] + ko);
                    bh[gg * 2][0] = r0; bh[gg * 2][1] = r1;
                    bh[gg * 2 + 1][0] = r2; bh[gg * 2 + 1][1] = r3;
                    ldsm4(r0, r1, r2, r3, bbase + TILE_BS + boff[ng] + ko);
                    bl[gg * 2][0] = r0; bl[gg * 2][1] = r1;
                    bl[gg * 2 + 1][0] = r2; bl[gg * 2 + 1][1] = r3;
                }
#pragma unroll
                for (int mt = 0; mt < 2; mt++)
#pragma unroll
                    for (int q = 0; q < 4; q++) {
                        int nf = half * 4 + q;
                        mma_bf16(acc[mt][nf], ah[mt][0], ah[mt][1], ah[mt][2], ah[mt][3],
                                 bh[q][0], bh[q][1]);
                        mma_bf16(acc[mt][nf], ah[mt][0], ah[mt][1], ah[mt][2], ah[mt][3],
                                 bl[q][0], bl[q][1]);
                        mma_bf16(acc[mt][nf], al[mt][0], al[mt][1], al[mt][2], al[mt][3],
                                 bh[q][0], bh[q][1]);
                    }
            }
        }
        __syncthreads();
    }

    float sdot[2][2] = {{0.f, 0.f}, {0.f, 0.f}};
#pragma unroll
    for (int mt = 0; mt < 2; mt++) {
        int r0 = rowBase + warp_m * 32 + mt * 16 + (lane >> 2);
        int r1 = r0 + 8;
#pragma unroll
        for (int nf = 0; nf < 8; nf++) {
            int col = colBase + warp_n * 64 + nf * 8 + (lane & 3) * 2;
            float b0 = bias[col], b1 = bias[col + 1];
            float w0 = Wp[col],   w1 = Wp[col + 1];
            float v00 = fmaxf(acc[mt][nf][0] + b0, 0.0f);
            float v01 = fmaxf(acc[mt][nf][1] + b1, 0.0f);
            float v10 = fmaxf(acc[mt][nf][2] + b0, 0.0f);
            float v11 = fmaxf(acc[mt][nf][3] + b1, 0.0f);
            *(float2*)(C + (size_t)r0 * 512 + col) = make_float2(v00, v01);
            *(float2*)(C + (size_t)r1 * 512 + col) = make_float2(v10, v11);
            sdot[mt][0] = fmaf(v00, w0, fmaf(v01, w1, sdot[mt][0]));
            sdot[mt][1] = fmaf(v10, w0, fmaf(v11, w1, sdot[mt][1]));
        }
    }
#pragma unroll
    for (int off = 1; off < 4; off <<= 1) {
#pragma unroll
        for (int mt = 0; mt < 2; mt++) {
            sdot[mt][0] += __shfl_xor_sync(0xffffffffu, sdot[mt][0], off);
            sdot[mt][1] += __shfl_xor_sync(0xffffffffu, sdot[mt][1], off);
        }
    }
    if ((lane & 3) == 0) {
#pragma unroll
        for (int mt = 0; mt < 2; mt++) {
            int r0 = rowBase + warp_m * 32 + mt * 16 + (lane >> 2);
            atomicAdd(&g_s0[r0], sdot[mt][0]);
            atomicAdd(&g_s0[r0 + 8], sdot[mt][1]);
        }
    }
}

// ---------------- score propagate (warp per row over CSR) ----------------
__global__ void k_score(const float* __restrict__ bp, int n) {
    int row = blockIdx.x * 8 + (threadIdx.x >> 5);
    if (row >= BATCH * n) return;
    int lane = threadIdx.x & 31;
    int b = row / n, bn = b * n;
    int start = g_rowstart[row];
    int cnt = g_cnt[row];
    float sum = 0.0f;
    for (int e = lane; e < cnt; e += 32) {
        int s = g_csr[b * NEDGE + start + e];
        sum += g_s0[bn + s] * rsqrtf((float)(g_cnt[bn + s] + 1));
    }
#pragma unroll
    for (int o = 16; o > 0; o >>= 1) sum += __shfl_down_sync(0xffffffffu, sum, o);
    if (lane == 0) {
        float deg = (float)(cnt + 1);
        g_score[row] = g_s0[row] / deg + rsqrtf(deg) * sum + bp[0];
    }
}

// ---------------- top-k: per-batch bitonic sort (+ tv store) ----------------
__global__ void k_topk(int n, int k) {
    extern __shared__ char sm[];
    float* sv = (float*)sm;
    int* si = (int*)(sv + n);
    int b = blockIdx.x, tid = threadIdx.x;
    for (int i = tid; i < n; i += blockDim.x) { sv[i] = g_score[b * n + i]; si[i] = i; }
    __syncthreads();
    for (int ksz = 2; ksz <= n; ksz <<= 1) {
        for (int j = ksz >> 1; j > 0; j >>= 1) {
            for (int i = tid; i < n; i += blockDim.x) {
                int ixj = i ^ j;
                if (ixj > i) {
                    float v1 = sv[i], v2 = sv[ixj];
                    int i1 = si[i], i2 = si[ixj];
                    bool before = (v1 > v2) || (v1 == v2 && i1 < i2);
                    bool desc = ((i & ksz) == 0);
                    if (desc ? !before : before) {
                        sv[i] = v2; sv[ixj] = v1; si[i] = i2; si[ixj] = i1;
                    }
                }
            }
            __syncthreads();
        }
    }
    for (int i = tid; i < n; i += blockDim.x) g_newidx[b * n + i] = -1;
    __syncthreads();
    for (int t = tid; t < k; t += blockDim.x) {
        int p = si[t];
        g_perm[b * n + t] = p;
        g_newidx[b * n + p] = t;
        g_tv[b * n + p] = tanhf(sv[t]);
    }
}

// ---------------- readout (max/mean over selected rows) ----------------
__global__ __launch_bounds__(128) void k_pool_readout(const float* __restrict__ h,
                                                      int n, int k, int first) {
    __shared__ float tv[1024];
    __shared__ int   pp[1024];
    const int b = blockIdx.x, fc = blockIdx.y, t = threadIdx.x;
    for (int r = t; r < k; r += 128) {
        int p = g_perm[b * n + r];
        pp[r] = p;
        tv[r] = g_tv[b * n + p];
    }
    __syncthreads();
    const int f = fc * 128 + t;
    float mx = -INFINITY, sm = 0.0f;
    for (int r = 0; r < k; r++) {
        float v = h[((size_t)b * n + pp[r]) * NHID + f] * tv[r];
        mx = fmaxf(mx, v);
        sm += v;
    }
    if (first) {
        g_z[b * 1024 + f] = mx;
        g_z[b * 1024 + 512 + f] = sm / (float)k;
    } else {
        g_z[b * 1024 + f] += mx;
        g_z[b * 1024 + 512 + f] += sm / (float)k;
    }
}

// ---------------- edge relabel + count for next stage ----------------
__global__ void k_edge_update_count(int n, int k) {
    int i = blockIdx.x * blockDim.x + threadIdx.x;
    if (i >= BATCH * NEDGE) return;
    int b = i / NEDGE;
    if (g_em[i] != 0.0f) {
        int ns = g_newidx[b * n + g_src[i]];
        int nd = g_newidx[b * n + g_dst[i]];
        if (ns >= 0 && nd >= 0) {
            g_src[i] = ns; g_dst[i] = nd;
            atomicAdd(&g_cnt[b * k + nd], 1);
        } else { g_em[i] = 0.0f; g_src[i] = 0; g_dst[i] = 0; }
    } else { g_src[i] = 0; g_dst[i] = 0; }
}

// ---------------- head ----------------
__global__ void k_head(const float* __restrict__ l1W, const float* __restrict__ l1b,
                       const float* __restrict__ l2W, const float* __restrict__ l2b,
                       const float* __restrict__ piW, const float* __restrict__ pib,
                       const float* __restrict__ vW, const float* __restrict__ vb,
                       float* __restrict__ out) {
    __shared__ float zz[1024];
    __shared__ float z1[512];
    __shared__ float z2[256];
    __shared__ float lg[128];
    __shared__ float stats[2];
    int b = blockIdx.x, tid = threadIdx.x;
    for (int i = tid; i < 1024; i += 256) zz[i] = g_z[b * 1024 + i];
    __syncthreads();
    for (int j = tid; j < 512; j += 256) {
        float a = l1b[j];
        for (int i = 0; i < 1024; i++) a = fmaf(zz[i], l1W[i * 512 + j], a);
        z1[j] = fmaxf(a, 0.0f);
    }
    __syncthreads();
    {
        int j = tid;
        float a = l2b[j];
        for (int i = 0; i < 512; i++) a = fmaf(z1[i], l2W[i * 256 + j], a);
        z2[j] = fmaxf(a, 0.0f);
    }
    __syncthreads();
    if (tid < 128) {
        float a = pib[tid];
        for (int i = 0; i < 256; i++) a = fmaf(z2[i], piW[i * 128 + tid], a);
        lg[tid] = a;
    } else if (tid == 128) {
        float a = vb[0];
        for (int i = 0; i < 256; i++) a = fmaf(z2[i], vW[i], a);
        out[BATCH * RULES + b] = fmaxf(a, 0.0f);
    }
    __syncthreads();
    if (tid == 0) {
        float mx = -INFINITY;
        for (int i = 0; i < 128; i++) mx = fmaxf(mx, lg[i]);
        float s = 0.0f;
        for (int i = 0; i < 128; i++) s += expf(lg[i] - mx);
        stats[0] = mx;
        stats[1] = logf(s);
    }
    __syncthreads();
    if (tid < 128) out[b * RULES + tid] = lg[tid] - stats[0] - stats[1];
}

// ---------------- host orchestration ----------------
extern "C" void kernel_launch(void* const* d_in, const int* in_sizes, int n_in,
                              void* d_out, int out_size) {
    const float* x    = (const float*)d_in[0];
    const int*   src  = (const int*)d_in[1];
    const int*   dst  = (const int*)d_in[2];
    const float* W1   = (const float*)d_in[3];
    const float* b1   = (const float*)d_in[4];
    const float* Wp1  = (const float*)d_in[5];
    const float* bp1  = (const float*)d_in[6];
    const float* W2   = (const float*)d_in[7];
    const float* b2   = (const float*)d_in[8];
    const float* Wp2  = (const float*)d_in[9];
    const float* bp2  = (const float*)d_in[10];
    const float* W3   = (const float*)d_in[11];
    const float* b3   = (const float*)d_in[12];
    const float* Wp3  = (const float*)d_in[13];
    const float* bp3  = (const float*)d_in[14];
    const float* l1W  = (const float*)d_in[15];
    const float* l1b  = (const float*)d_in[16];
    const float* l2W  = (const float*)d_in[17];
    const float* l2b  = (const float*)d_in[18];
    const float* piW  = (const float*)d_in[19];
    const float* pib  = (const float*)d_in[20];
    const float* vW   = (const float*)d_in[21];
    const float* vb   = (const float*)d_in[22];
    float* out = (float*)d_out;

    float *pA = nullptr, *pB = nullptr;
    __nv_bfloat16 *ahi = nullptr, *alo = nullptr;
    __nv_bfloat16 (*whi)[NHID * NHID] = nullptr, (*wlo)[NHID * NHID] = nullptr;
    cudaGetSymbolAddress((void**)&pA, g_bufA);
    cudaGetSymbolAddress((void**)&pB, g_bufB);
    cudaGetSymbolAddress((void**)&ahi, g_ahi);
    cudaGetSymbolAddress((void**)&alo, g_alo);
    cudaGetSymbolAddress((void**)&whi, g_whi);
    cudaGetSymbolAddress((void**)&wlo, g_wlo);

    cudaFuncSetAttribute(k_gemm_mma, cudaFuncAttributeMaxDynamicSharedMemorySize, GEMM_SMEM);

    const int EB = BATCH * NEDGE;

    k_zero_cnt<<<(BATCH * NMAX + 255) / 256, 256>>>(BATCH * NMAX);
    k_init_edges_count<<<(EB + 255) / 256, 256>>>(src, dst);
    // all weight splits off the critical path
    k_split_w<<<dim3(FIN / 32, 16),  dim3(32, 8)>>>(W1, whi[0], wlo[0], FIN);
    k_split_w<<<dim3(NHID / 32, 16), dim3(32, 8)>>>(W2, whi[1], wlo[1], NHID);
    k_split_w<<<dim3(NHID / 32, 16), dim3(32, 8)>>>(W3, whi[2], wlo[2], NHID);

    // ---- stage 1: n=2048, K=256 ----
    k_scan_fill<<<BATCH, 1024>>>(2048, 0);
    k_gather_w<2><<<BATCH * 2048 / 8, 256>>>(x, ahi, alo, 2048);
    k_gemm_mma<<<dim3(2, BATCH * 2048 / 128), 512, GEMM_SMEM>>>(
        ahi, alo, whi[0], wlo[0], pA, b1, Wp1, BATCH * 2048, FIN);
    k_score<<<BATCH * 2048 / 8, 256>>>(bp1, 2048);
    k_topk<<<BATCH, 1024, 2048 * 8>>>(2048, 1024);
    k_pool_readout<<<dim3(BATCH, 4), 128>>>(pA, 2048, 1024, 1);
    k_zero_cnt<<<(BATCH * 1024 + 255) / 256, 256>>>(BATCH * 1024);
    k_edge_update_count<<<(EB + 255) / 256, 256>>>(2048, 1024);

    // ---- stage 2: n=1024, K=512 ----
    k_scan_fill<<<BATCH, 1024>>>(1024, 2048);
    k_gather_w<4><<<BATCH * 1024 / 8, 256>>>(pA, ahi, alo, 1024);
    k_gemm_mma<<<dim3(2, BATCH * 1024 / 128), 512, GEMM_SMEM>>>(
        ahi, alo, whi[1], wlo[1], pB, b2, Wp2, BATCH * 1024, NHID);
    k_score<<<BATCH * 1024 / 8, 256>>>(bp2, 1024);
    k_topk<<<BATCH, 1024, 1024 * 8>>>(1024, 512);
    k_pool_readout<<<dim3(BATCH, 4), 128>>>(pB, 1024, 512, 0);
    k_zero_cnt<<<(BATCH * 512 + 255) / 256, 256>>>(BATCH * 512);
    k_edge_update_count<<<(EB + 255) / 256, 256>>>(1024, 512);

    // ---- stage 3: n=512, K=512 ----
    k_scan_fill<<<BATCH, 1024>>>(512, 1024);
    k_gather_w<4><<<BATCH * 512 / 8, 256>>>(pB, ahi, alo, 512);
    k_gemm_mma<<<dim3(2, BATCH * 512 / 128), 512, GEMM_SMEM>>>(
        ahi, alo, whi[2], wlo[2], pA, b3, Wp3, BATCH * 512, NHID);
    k_score<<<BATCH * 512 / 8, 256>>>(bp3, 512);
    k_topk<<<BATCH, 1024, 512 * 8>>>(512, 256);
    k_pool_readout<<<dim3(BATCH, 4), 128>>>(pA, 512, 256, 0);

    k_head<<<BATCH, 256>>>(l1W, l1b, l2W, l2b, piW, pib, vW, vb, out);
}

// round 14
// speedup vs baseline: 1.0214x; 1.0159x over previous
#include <cuda_runtime.h>
#include <cuda_bf16.h>
#include <math.h>
#include <stdint.h>

#define BATCH 64
#define NMAX  2048
#define NEDGE 32768
#define FIN   256
#define NHID  512
#define RULES 128

// ---------------- scratch (device globals; no allocations) ----------------
static __device__ float g_bufA[(size_t)BATCH * NMAX * NHID];   // gemm outputs (ping)
static __device__ float g_bufB[(size_t)BATCH * NMAX * NHID];   // gemm outputs (pong)
static __device__ __align__(16) __nv_bfloat16 g_ahi[(size_t)BATCH * NMAX * NHID / 2];
static __device__ __align__(16) __nv_bfloat16 g_alo[(size_t)BATCH * NMAX * NHID / 2];
static __device__ __align__(16) __nv_bfloat16 g_whi[3][NHID * NHID];
static __device__ __align__(16) __nv_bfloat16 g_wlo[3][NHID * NHID];
static __device__ int   g_cnt[BATCH * NMAX];
static __device__ int   g_rowstart[BATCH * NMAX];
static __device__ int   g_csr[BATCH * NEDGE];
static __device__ int2  g_sinfo[BATCH * NMAX];   // (old-space row, bitcast(coef incl tv))
static __device__ float g_s0[BATCH * NMAX];
static __device__ float g_score[BATCH * NMAX];
static __device__ float g_tv[BATCH * NMAX];
static __device__ int   g_perm[BATCH * NMAX];
static __device__ int   g_newidx[BATCH * NMAX];
static __device__ int   g_src[BATCH * NEDGE];
static __device__ int   g_dst[BATCH * NEDGE];
static __device__ float g_em[BATCH * NEDGE];
static __device__ float g_z[BATCH * 2 * NHID];

// ---------------- helpers ----------------
__device__ __forceinline__ uint32_t smem_u32(const void* p) {
    uint32_t a;
    asm("{ .reg .u64 t; cvta.to.shared.u64 t, %1; cvt.u32.u64 %0, t; }" : "=r"(a) : "l"(p));
    return a;
}
__device__ __forceinline__ void cp16(uint32_t saddr, const void* gptr) {
    asm volatile("cp.async.cg.shared.global [%0], [%1], 16;"
                 :: "r"(saddr), "l"(__cvta_generic_to_global(gptr)) : "memory");
}
__device__ __forceinline__ void ldsm4(uint32_t& r0, uint32_t& r1, uint32_t& r2, uint32_t& r3,
                                      uint32_t addr) {
    asm volatile("ldmatrix.sync.aligned.m8n8.x4.shared.b16 {%0,%1,%2,%3}, [%4];"
                 : "=r"(r0), "=r"(r1), "=r"(r2), "=r"(r3) : "r"(addr));
}
__device__ __forceinline__ void mma_bf16(float* c, uint32_t a0, uint32_t a1, uint32_t a2,
                                         uint32_t a3, uint32_t b0, uint32_t b1) {
    asm volatile(
        "mma.sync.aligned.m16n8k16.row.col.f32.bf16.bf16.f32 "
        "{%0,%1,%2,%3}, {%4,%5,%6,%7}, {%8,%9}, {%0,%1,%2,%3};"
        : "+f"(c[0]), "+f"(c[1]), "+f"(c[2]), "+f"(c[3])
        : "r"(a0), "r"(a1), "r"(a2), "r"(a3), "r"(b0), "r"(b1));
}
__device__ __forceinline__ uint32_t pk2(float a, float b) {
    __nv_bfloat162 t = __floats2bfloat162_rn(a, b);
    return *(uint32_t*)&t;
}

// ---------------- init ----------------
__global__ void k_zero_cnt(int total) {
    int i = blockIdx.x * blockDim.x + threadIdx.x;
    if (i < total) g_cnt[i] = 0;
}
__global__ void k_init_edges_count(const int* __restrict__ src, const int* __restrict__ dst) {
    int i = blockIdx.x * blockDim.x + threadIdx.x;
    if (i >= BATCH * NEDGE) return;
    int s = src[i], d = dst[i];
    g_src[i] = s; g_dst[i] = d; g_em[i] = 1.0f;
    int b = i / NEDGE;
    atomicAdd(&g_cnt[b * NMAX + d], 1);
}

// ---------------- fused per-batch scan + CSR fill + s0 zero + sinfo build ----------------
// n_old == 0 -> stage 1 (identity indirection)
__global__ __launch_bounds__(1024) void k_scan_fill(int n, int n_old) {
    __shared__ int buf[2][NMAX];
    __shared__ int cur[NMAX];
    int b = blockIdx.x, tid = threadIdx.x;
    for (int i = tid; i < n; i += 1024) buf[0][i] = g_cnt[b * n + i];
    __syncthreads();
    int s = 0;
    for (int d = 1; d < n; d <<= 1) {
        for (int i = tid; i < n; i += 1024) {
            int v = buf[s][i];
            if (i >= d) v += buf[s][i - d];
            buf[s ^ 1][i] = v;
        }
        __syncthreads();
        s ^= 1;
    }
    for (int i = tid; i < n; i += 1024) {
        int excl = (i == 0) ? 0 : buf[s][i - 1];
        g_rowstart[b * n + i] = excl;
        cur[i] = excl;
        g_s0[b * n + i] = 0.0f;
        int ci = g_cnt[b * n + i];
        float c = rsqrtf((float)(ci + 1));
        int2 si;
        if (n_old) {
            int p = g_perm[b * n_old + i];
            int old = b * n_old + p;
            si.x = old;
            si.y = __float_as_int(g_tv[old] * c);
        } else {
            si.x = b * n + i;
            si.y = __float_as_int(c);
        }
        g_sinfo[b * n + i] = si;
    }
    __syncthreads();
    for (int e = tid; e < NEDGE; e += 1024) {
        int i = b * NEDGE + e;
        if (g_em[i] != 0.0f) {
            int pos = atomicAdd(&cur[g_dst[i]], 1);
            g_csr[b * NEDGE + pos] = g_src[i];
        }
    }
}

// ---------------- warp-per-row GCN aggregation + bf16 split ----------------
template<int VEC>
__global__ __launch_bounds__(256) void k_gather_w(const float* __restrict__ xin,
                                                  __nv_bfloat16* __restrict__ hi,
                                                  __nv_bfloat16* __restrict__ lo,
                                                  int n) {
    const int K = VEC * 128;
    const int gw = (blockIdx.x * 256 + threadIdx.x) >> 5;
    const int lane = threadIdx.x & 31;
    const int b = gw / n;
    const int bn = b * n;
    const int start = g_rowstart[gw];
    const int cnt = g_cnt[gw];
    const float dinv = rsqrtf((float)(cnt + 1));
    const int2 sself = g_sinfo[gw];

    float4 acc[VEC];
#pragma unroll
    for (int j = 0; j < VEC; j++) acc[j] = make_float4(0.f, 0.f, 0.f, 0.f);

    for (int base = 0; base < cnt; base += 32) {
        int m = min(32, cnt - base);
        int off = 0; float c = 0.0f;
        if (lane < m) {
            int s = g_csr[b * NEDGE + start + base + lane];
            int2 si = g_sinfo[bn + s];
            off = si.x * K;
            c = __int_as_float(si.y);
        }
#pragma unroll 8
        for (int e = 0; e < m; e++) {
            int o = __shfl_sync(0xffffffffu, off, e);
            float cc = __shfl_sync(0xffffffffu, c, e);
            const float4* p = (const float4*)(xin + o);
#pragma unroll
            for (int j = 0; j < VEC; j++) {
                float4 v = p[lane + j * 32];
                acc[j].x = fmaf(v.x, cc, acc[j].x);
                acc[j].y = fmaf(v.y, cc, acc[j].y);
                acc[j].z = fmaf(v.z, cc, acc[j].z);
                acc[j].w = fmaf(v.w, cc, acc[j].w);
            }
        }
    }
    const float scoef = __int_as_float(sself.y);
    const float4* selfp = (const float4*)(xin + (size_t)sself.x * K);
    uint2* hp = (uint2*)(hi + (size_t)gw * K);
    uint2* lp = (uint2*)(lo + (size_t)gw * K);
#pragma unroll
    for (int j = 0; j < VEC; j++) {
        float4 sv = selfp[lane + j * 32];
        float rx = dinv * fmaf(sv.x, scoef, acc[j].x);
        float ry = dinv * fmaf(sv.y, scoef, acc[j].y);
        float rz = dinv * fmaf(sv.z, scoef, acc[j].z);
        float rw = dinv * fmaf(sv.w, scoef, acc[j].w);
        float lx = rx - __bfloat162float(__float2bfloat16(rx));
        float ly = ry - __bfloat162float(__float2bfloat16(ry));
        float lz = rz - __bfloat162float(__float2bfloat16(rz));
        float lw = rw - __bfloat162float(__float2bfloat16(rw));
        hp[lane + j * 32] = make_uint2(pk2(rx, ry), pk2(rz, rw));
        lp[lane + j * 32] = make_uint2(pk2(lx, ly), pk2(lz, lw));
    }
}

// ---------------- weight split + transpose via smem tile ----------------
__global__ void k_split_w(const float* __restrict__ W, __nv_bfloat16* __restrict__ hi,
                          __nv_bfloat16* __restrict__ lo, int K) {
    __shared__ float tile[32][33];
    const int k0 = blockIdx.x * 32, n0 = blockIdx.y * 32;
    const int tx = threadIdx.x, ty = threadIdx.y;
#pragma unroll
    for (int j = 0; j < 4; j++) {
        int kr = ty + j * 8;
        tile[kr][tx] = W[(size_t)(k0 + kr) * 512 + n0 + tx];
    }
    __syncthreads();
#pragma unroll
    for (int j = 0; j < 4; j++) {
        int nr = ty + j * 8;
        float v = tile[tx][nr];
        __nv_bfloat16 h = __float2bfloat16(v);
        size_t o = (size_t)(n0 + nr) * K + k0 + tx;
        hi[o] = h;
        lo[o] = __float2bfloat16(v - __bfloat162float(h));
    }
}

// ---------------- split-bf16 tensor GEMM + fused bias/relu/scorer epilogue ----------------
// single __syncthreads per K-chunk: wait -> sync -> issue load(t+2) -> compute(t)
#define LDS_E   40
#define TILE_A  (128 * LDS_E * 2)
#define TILE_BS (256 * LDS_E * 2)
#define STAGE_B (2 * TILE_A + 2 * TILE_BS)
#define GEMM_SMEM (3 * STAGE_B)
__global__ __launch_bounds__(512, 1) void k_gemm_mma(
    const __nv_bfloat16* __restrict__ Ahi, const __nv_bfloat16* __restrict__ Alo,
    const __nv_bfloat16* __restrict__ Bhi, const __nv_bfloat16* __restrict__ Blo,
    float* __restrict__ C, const float* __restrict__ bias, const float* __restrict__ Wp,
    int M, int K)
{
    extern __shared__ __align__(128) char smem[];
    const uint32_t sb = smem_u32(smem);
    const int tid = threadIdx.x;
    const int wid = tid >> 5;
    const int lane = tid & 31;
    const int warp_m = wid & 3;
    const int warp_n = wid >> 2;
    const int rowBase = blockIdx.y * 128;
    const int colBase = blockIdx.x * 256;

    const int g = lane >> 3;
    const int a_m = lane & 15;
    const int a_k = (lane >> 4) << 3;
    const int b_n = lane - ((g == 0) ? 0 : (g == 3) ? 16 : 8);
    const int b_k = (g & 1) << 3;

    uint32_t aoff[2], boff[4];
#pragma unroll
    for (int mt = 0; mt < 2; mt++)
        aoff[mt] = ((warp_m * 32 + mt * 16 + a_m) * LDS_E + a_k) * 2;
#pragma unroll
    for (int ng = 0; ng < 4; ng++)
        boff[ng] = ((warp_n * 64 + ng * 16 + b_n) * LDS_E + b_k) * 2;

    float acc[2][8][4];
#pragma unroll
    for (int mt = 0; mt < 2; mt++)
#pragma unroll
        for (int nf = 0; nf < 8; nf++)
#pragma unroll
            for (int e = 0; e < 4; e++) acc[mt][nf][e] = 0.0f;

    const int nch = K >> 5;

    auto load_stage = [&](int t) {
        const uint32_t base = sb + (t % 3) * STAGE_B;
        const int kc0 = t << 5;
        {
            int r = tid >> 2, blk = tid & 3;
            uint32_t so = r * (LDS_E * 2) + blk * 16;
            size_t ga = (size_t)(rowBase + r) * K + kc0 + blk * 8;
            cp16(base + so,          Ahi + ga);
            cp16(base + TILE_A + so, Alo + ga);
        }
#pragma unroll
        for (int part = 0; part < 2; part++) {
            int idx = tid + part * 512;
            int r = idx >> 2, blk = idx & 3;
            uint32_t so = r * (LDS_E * 2) + blk * 16;
            size_t gb = (size_t)(colBase + r) * K + kc0 + blk * 8;
            cp16(base + 2 * TILE_A + so,           Bhi + gb);
            cp16(base + 2 * TILE_A + TILE_BS + so, Blo + gb);
        }
        asm volatile("cp.async.commit_group;" ::: "memory");
    };

    load_stage(0);
    if (nch > 1) load_stage(1);
    for (int t = 0; t < nch; t++) {
        // ensure group t complete; allow group t+1 in flight
        if (t == nch - 1) {
            asm volatile("cp.async.wait_group 0;" ::: "memory");
        } else {
            asm volatile("cp.async.wait_group 1;" ::: "memory");
        }
        __syncthreads();   // also guards buffer (t-1)%3 reuse by load(t+2) below
        if (t + 2 < nch) load_stage(t + 2);

        const uint32_t base = sb + (t % 3) * STAGE_B;
        const uint32_t bbase = base + 2 * TILE_A;
#pragma unroll
        for (int kk = 0; kk < 2; kk++) {
            const uint32_t ko = kk * 32;
            uint32_t ah[2][4], al[2][4];
#pragma unroll
            for (int mt = 0; mt < 2; mt++) {
                ldsm4(ah[mt][0], ah[mt][1], ah[mt][2], ah[mt][3], base + aoff[mt] + ko);
                ldsm4(al[mt][0], al[mt][1], al[mt][2], al[mt][3], base + TILE_A + aoff[mt] + ko);
            }
#pragma unroll
            for (int half = 0; half < 2; half++) {
                uint32_t bh[4][2], bl[4][2];
#pragma unroll
                for (int gg = 0; gg < 2; gg++) {
                    int ng = half * 2 + gg;
                    uint32_t r0, r1, r2, r3;
                    ldsm4(r0, r1, r2, r3, bbase + boff[ng] + ko);
                    bh[gg * 2][0] = r0; bh[gg * 2][1] = r1;
                    bh[gg * 2 + 1][0] = r2; bh[gg * 2 + 1][1] = r3;
                    ldsm4(r0, r1, r2, r3, bbase + TILE_BS + boff[ng] + ko);
                    bl[gg * 2][0] = r0; bl[gg * 2][1] = r1;
                    bl[gg * 2 + 1][0] = r2; bl[gg * 2 + 1][1] = r3;
                }
#pragma unroll
                for (int mt = 0; mt < 2; mt++)
#pragma unroll
                    for (int q = 0; q < 4; q++) {
                        int nf = half * 4 + q;
                        mma_bf16(acc[mt][nf], ah[mt][0], ah[mt][1], ah[mt][2], ah[mt][3],
                                 bh[q][0], bh[q][1]);
                        mma_bf16(acc[mt][nf], ah[mt][0], ah[mt][1], ah[mt][2], ah[mt][3],
                                 bl[q][0], bl[q][1]);
                        mma_bf16(acc[mt][nf], al[mt][0], al[mt][1], al[mt][2], al[mt][3],
                                 bh[q][0], bh[q][1]);
                    }
            }
        }
    }

    float sdot[2][2] = {{0.f, 0.f}, {0.f, 0.f}};
#pragma unroll
    for (int mt = 0; mt < 2; mt++) {
        int r0 = rowBase + warp_m * 32 + mt * 16 + (lane >> 2);
        int r1 = r0 + 8;
#pragma unroll
        for (int nf = 0; nf < 8; nf++) {
            int col = colBase + warp_n * 64 + nf * 8 + (lane & 3) * 2;
            float b0 = bias[col], b1 = bias[col + 1];
            float w0 = Wp[col],   w1 = Wp[col + 1];
            float v00 = fmaxf(acc[mt][nf][0] + b0, 0.0f);
            float v01 = fmaxf(acc[mt][nf][1] + b1, 0.0f);
            float v10 = fmaxf(acc[mt][nf][2] + b0, 0.0f);
            float v11 = fmaxf(acc[mt][nf][3] + b1, 0.0f);
            *(float2*)(C + (size_t)r0 * 512 + col) = make_float2(v00, v01);
            *(float2*)(C + (size_t)r1 * 512 + col) = make_float2(v10, v11);
            sdot[mt][0] = fmaf(v00, w0, fmaf(v01, w1, sdot[mt][0]));
            sdot[mt][1] = fmaf(v10, w0, fmaf(v11, w1, sdot[mt][1]));
        }
    }
#pragma unroll
    for (int off = 1; off < 4; off <<= 1) {
#pragma unroll
        for (int mt = 0; mt < 2; mt++) {
            sdot[mt][0] += __shfl_xor_sync(0xffffffffu, sdot[mt][0], off);
            sdot[mt][1] += __shfl_xor_sync(0xffffffffu, sdot[mt][1], off);
        }
    }
    if ((lane & 3) == 0) {
#pragma unroll
        for (int mt = 0; mt < 2; mt++) {
            int r0 = rowBase + warp_m * 32 + mt * 16 + (lane >> 2);
            atomicAdd(&g_s0[r0], sdot[mt][0]);
            atomicAdd(&g_s0[r0 + 8], sdot[mt][1]);
        }
    }
}

// ---------------- score propagate (warp per row over CSR) ----------------
__global__ void k_score(const float* __restrict__ bp, int n) {
    int row = blockIdx.x * 8 + (threadIdx.x >> 5);
    if (row >= BATCH * n) return;
    int lane = threadIdx.x & 31;
    int b = row / n, bn = b * n;
    int start = g_rowstart[row];
    int cnt = g_cnt[row];
    float sum = 0.0f;
    for (int e = lane; e < cnt; e += 32) {
        int s = g_csr[b * NEDGE + start + e];
        sum += g_s0[bn + s] * rsqrtf((float)(g_cnt[bn + s] + 1));
    }
#pragma unroll
    for (int o = 16; o > 0; o >>= 1) sum += __shfl_down_sync(0xffffffffu, sum, o);
    if (lane == 0) {
        float deg = (float)(cnt + 1);
        g_score[row] = g_s0[row] / deg + rsqrtf(deg) * sum + bp[0];
    }
}

// ---------------- top-k: per-batch bitonic sort (+ tv store, next-stage cnt zero) ----------------
__global__ void k_topk(int n, int k, int kzero) {
    extern __shared__ char sm[];
    float* sv = (float*)sm;
    int* si = (int*)(sv + n);
    int b = blockIdx.x, tid = threadIdx.x;
    for (int i = tid; i < n; i += blockDim.x) { sv[i] = g_score[b * n + i]; si[i] = i; }
    __syncthreads();
    for (int ksz = 2; ksz <= n; ksz <<= 1) {
        for (int j = ksz >> 1; j > 0; j >>= 1) {
            for (int i = tid; i < n; i += blockDim.x) {
                int ixj = i ^ j;
                if (ixj > i) {
                    float v1 = sv[i], v2 = sv[ixj];
                    int i1 = si[i], i2 = si[ixj];
                    bool before = (v1 > v2) || (v1 == v2 && i1 < i2);
                    bool desc = ((i & ksz) == 0);
                    if (desc ? !before : before) {
                        sv[i] = v2; sv[ixj] = v1; si[i] = i2; si[ixj] = i1;
                    }
                }
            }
            __syncthreads();
        }
    }
    for (int i = tid; i < n; i += blockDim.x) g_newidx[b * n + i] = -1;
    __syncthreads();
    for (int t = tid; t < k; t += blockDim.x) {
        int p = si[t];
        g_perm[b * n + t] = p;
        g_newidx[b * n + p] = t;
        g_tv[b * n + p] = tanhf(sv[t]);
    }
    if (kzero)
        for (int j = tid; j < kzero; j += blockDim.x) g_cnt[b * kzero + j] = 0;
}

// ---------------- readout (max/mean over selected rows) ----------------
__global__ __launch_bounds__(128) void k_pool_readout(const float* __restrict__ h,
                                                      int n, int k, int first) {
    __shared__ float tv[1024];
    __shared__ int   pp[1024];
    const int b = blockIdx.x, fc = blockIdx.y, t = threadIdx.x;
    for (int r = t; r < k; r += 128) {
        int p = g_perm[b * n + r];
        pp[r] = p;
        tv[r] = g_tv[b * n + p];
    }
    __syncthreads();
    const int f = fc * 128 + t;
    float mx = -INFINITY, sm = 0.0f;
    for (int r = 0; r < k; r++) {
        float v = h[((size_t)b * n + pp[r]) * NHID + f] * tv[r];
        mx = fmaxf(mx, v);
        sm += v;
    }
    if (first) {
        g_z[b * 1024 + f] = mx;
        g_z[b * 1024 + 512 + f] = sm / (float)k;
    } else {
        g_z[b * 1024 + f] += mx;
        g_z[b * 1024 + 512 + f] += sm / (float)k;
    }
}

// ---------------- edge relabel + count for next stage ----------------
__global__ void k_edge_update_count(int n, int k) {
    int i = blockIdx.x * blockDim.x + threadIdx.x;
    if (i >= BATCH * NEDGE) return;
    int b = i / NEDGE;
    if (g_em[i] != 0.0f) {
        int ns = g_newidx[b * n + g_src[i]];
        int nd = g_newidx[b * n + g_dst[i]];
        if (ns >= 0 && nd >= 0) {
            g_src[i] = ns; g_dst[i] = nd;
            atomicAdd(&g_cnt[b * k + nd], 1);
        } else { g_em[i] = 0.0f; g_src[i] = 0; g_dst[i] = 0; }
    } else { g_src[i] = 0; g_dst[i] = 0; }
}

// ---------------- head ----------------
__global__ void k_head(const float* __restrict__ l1W, const float* __restrict__ l1b,
                       const float* __restrict__ l2W, const float* __restrict__ l2b,
                       const float* __restrict__ piW, const float* __restrict__ pib,
                       const float* __restrict__ vW, const float* __restrict__ vb,
                       float* __restrict__ out) {
    __shared__ float zz[1024];
    __shared__ float z1[512];
    __shared__ float z2[256];
    __shared__ float lg[128];
    __shared__ float stats[2];
    int b = blockIdx.x, tid = threadIdx.x;
    for (int i = tid; i < 1024; i += 256) zz[i] = g_z[b * 1024 + i];
    __syncthreads();
    for (int j = tid; j < 512; j += 256) {
        float a = l1b[j];
        for (int i = 0; i < 1024; i++) a = fmaf(zz[i], l1W[i * 512 + j], a);
        z1[j] = fmaxf(a, 0.0f);
    }
    __syncthreads();
    {
        int j = tid;
        float a = l2b[j];
        for (int i = 0; i < 512; i++) a = fmaf(z1[i], l2W[i * 256 + j], a);
        z2[j] = fmaxf(a, 0.0f);
    }
    __syncthreads();
    if (tid < 128) {
        float a = pib[tid];
        for (int i = 0; i < 256; i++) a = fmaf(z2[i], piW[i * 128 + tid], a);
        lg[tid] = a;
    } else if (tid == 128) {
        float a = vb[0];
        for (int i = 0; i < 256; i++) a = fmaf(z2[i], vW[i], a);
        out[BATCH * RULES + b] = fmaxf(a, 0.0f);
    }
    __syncthreads();
    if (tid == 0) {
        float mx = -INFINITY;
        for (int i = 0; i < 128; i++) mx = fmaxf(mx, lg[i]);
        float s = 0.0f;
        for (int i = 0; i < 128; i++) s += expf(lg[i] - mx);
        stats[0] = mx;
        stats[1] = logf(s);
    }
    __syncthreads();
    if (tid < 128) out[b * RULES + tid] = lg[tid] - stats[0] - stats[1];
}

// ---------------- host orchestration ----------------
extern "C" void kernel_launch(void* const* d_in, const int* in_sizes, int n_in,
                              void* d_out, int out_size) {
    const float* x    = (const float*)d_in[0];
    const int*   src  = (const int*)d_in[1];
    const int*   dst  = (const int*)d_in[2];
    const float* W1   = (const float*)d_in[3];
    const float* b1   = (const float*)d_in[4];
    const float* Wp1  = (const float*)d_in[5];
    const float* bp1  = (const float*)d_in[6];
    const float* W2   = (const float*)d_in[7];
    const float* b2   = (const float*)d_in[8];
    const float* Wp2  = (const float*)d_in[9];
    const float* bp2  = (const float*)d_in[10];
    const float* W3   = (const float*)d_in[11];
    const float* b3   = (const float*)d_in[12];
    const float* Wp3  = (const float*)d_in[13];
    const float* bp3  = (const float*)d_in[14];
    const float* l1W  = (const float*)d_in[15];
    const float* l1b  = (const float*)d_in[16];
    const float* l2W  = (const float*)d_in[17];
    const float* l2b  = (const float*)d_in[18];
    const float* piW  = (const float*)d_in[19];
    const float* pib  = (const float*)d_in[20];
    const float* vW   = (const float*)d_in[21];
    const float* vb   = (const float*)d_in[22];
    float* out = (float*)d_out;

    float *pA = nullptr, *pB = nullptr;
    __nv_bfloat16 *ahi = nullptr, *alo = nullptr;
    __nv_bfloat16 (*whi)[NHID * NHID] = nullptr, (*wlo)[NHID * NHID] = nullptr;
    cudaGetSymbolAddress((void**)&pA, g_bufA);
    cudaGetSymbolAddress((void**)&pB, g_bufB);
    cudaGetSymbolAddress((void**)&ahi, g_ahi);
    cudaGetSymbolAddress((void**)&alo, g_alo);
    cudaGetSymbolAddress((void**)&whi, g_whi);
    cudaGetSymbolAddress((void**)&wlo, g_wlo);

    cudaFuncSetAttribute(k_gemm_mma, cudaFuncAttributeMaxDynamicSharedMemorySize, GEMM_SMEM);

    const int EB = BATCH * NEDGE;

    // launch order: capture slot #4 = k_scan_fill (stage-1) for next-round evidence
    k_zero_cnt<<<(BATCH * NMAX + 255) / 256, 256>>>(BATCH * NMAX);          // 1
    k_init_edges_count<<<(EB + 255) / 256, 256>>>(src, dst);                // 2
    k_split_w<<<dim3(FIN / 32, 16),  dim3(32, 8)>>>(W1, whi[0], wlo[0], FIN); // 3
    // ---- stage 1: n=2048, K=256 ----
    k_scan_fill<<<BATCH, 1024>>>(2048, 0);                                  // 4 (captured)
    k_gather_w<2><<<BATCH * 2048 / 8, 256>>>(x, ahi, alo, 2048);
    k_gemm_mma<<<dim3(2, BATCH * 2048 / 128), 512, GEMM_SMEM>>>(
        ahi, alo, whi[0], wlo[0], pA, b1, Wp1, BATCH * 2048, FIN);
    k_split_w<<<dim3(NHID / 32, 16), dim3(32, 8)>>>(W2, whi[1], wlo[1], NHID);
    k_split_w<<<dim3(NHID / 32, 16), dim3(32, 8)>>>(W3, whi[2], wlo[2], NHID);
    k_score<<<BATCH * 2048 / 8, 256>>>(bp1, 2048);
    k_topk<<<BATCH, 1024, 2048 * 8>>>(2048, 1024, 1024);
    k_pool_readout<<<dim3(BATCH, 4), 128>>>(pA, 2048, 1024, 1);
    k_edge_update_count<<<(EB + 255) / 256, 256>>>(2048, 1024);

    // ---- stage 2: n=1024, K=512 ----
    k_scan_fill<<<BATCH, 1024>>>(1024, 2048);
    k_gather_w<4><<<BATCH * 1024 / 8, 256>>>(pA, ahi, alo, 1024);
    k_gemm_mma<<<dim3(2, BATCH * 1024 / 128), 512, GEMM_SMEM>>>(
        ahi, alo, whi[1], wlo[1], pB, b2, Wp2, BATCH * 1024, NHID);
    k_score<<<BATCH * 1024 / 8, 256>>>(bp2, 1024);
    k_topk<<<BATCH, 1024, 1024 * 8>>>(1024, 512, 512);
    k_pool_readout<<<dim3(BATCH, 4), 128>>>(pB, 1024, 512, 0);
    k_edge_update_count<<<(EB + 255) / 256, 256>>>(1024, 512);

    // ---- stage 3: n=512, K=512 ----
    k_scan_fill<<<BATCH, 1024>>>(512, 1024);
    k_gather_w<4><<<BATCH * 512 / 8, 256>>>(pB, ahi, alo, 512);
    k_gemm_mma<<<dim3(2, BATCH * 512 / 128), 512, GEMM_SMEM>>>(
        ahi, alo, whi[2], wlo[2], pA, b3, Wp3, BATCH * 512, NHID);
    k_score<<<BATCH * 512 / 8, 256>>>(bp3, 512);
    k_topk<<<BATCH, 1024, 512 * 8>>>(512, 256, 0);
    k_pool_readout<<<dim3(BATCH, 4), 128>>>(pA, 512, 256, 0);

    k_head<<<BATCH, 256>>>(l1W, l1b, l2W, l2b, piW, pib, vW, vb, out);
}

// round 16
// speedup vs baseline: 1.0346x; 1.0129x over previous
#include <cuda_runtime.h>
#include <cuda_bf16.h>
#include <math.h>
#include <stdint.h>

#define BATCH 64
#define NMAX  2048
#define NEDGE 32768
#define FIN   256
#define NHID  512
#define RULES 128

// ---------------- scratch (device globals; no allocations) ----------------
static __device__ float g_bufA[(size_t)BATCH * NMAX * NHID];   // gemm outputs (ping)
static __device__ float g_bufB[(size_t)BATCH * NMAX * NHID];   // gemm outputs (pong)
static __device__ __align__(16) __nv_bfloat16 g_ahi[(size_t)BATCH * NMAX * NHID / 2];
static __device__ __align__(16) __nv_bfloat16 g_alo[(size_t)BATCH * NMAX * NHID / 2];
static __device__ __align__(16) __nv_bfloat16 g_whi[3][NHID * NHID];
static __device__ __align__(16) __nv_bfloat16 g_wlo[3][NHID * NHID];
static __device__ int   g_cnt[BATCH * NMAX];
static __device__ int   g_rowstart[BATCH * NMAX];
static __device__ int   g_csr[BATCH * NEDGE];
static __device__ int2  g_sinfo[BATCH * NMAX];   // (old-space row, bitcast(coef incl tv))
static __device__ float g_s0[BATCH * NMAX];
static __device__ float g_score[BATCH * NMAX];
static __device__ float g_tv[BATCH * NMAX];
static __device__ int   g_perm[BATCH * NMAX];
static __device__ int   g_newidx[BATCH * NMAX];
static __device__ int2  g_edge[BATCH * NEDGE];   // (src,dst); invalid: dst = -1
static __device__ float g_z[BATCH * 2 * NHID];

// ---------------- helpers ----------------
__device__ __forceinline__ uint32_t smem_u32(const void* p) {
    uint32_t a;
    asm("{ .reg .u64 t; cvta.to.shared.u64 t, %1; cvt.u32.u64 %0, t; }" : "=r"(a) : "l"(p));
    return a;
}
__device__ __forceinline__ void cp16(uint32_t saddr, const void* gptr) {
    asm volatile("cp.async.cg.shared.global [%0], [%1], 16;"
                 :: "r"(saddr), "l"(__cvta_generic_to_global(gptr)) : "memory");
}
__device__ __forceinline__ void ldsm4(uint32_t& r0, uint32_t& r1, uint32_t& r2, uint32_t& r3,
                                      uint32_t addr) {
    asm volatile("ldmatrix.sync.aligned.m8n8.x4.shared.b16 {%0,%1,%2,%3}, [%4];"
                 : "=r"(r0), "=r"(r1), "=r"(r2), "=r"(r3) : "r"(addr));
}
__device__ __forceinline__ void mma_bf16(float* c, uint32_t a0, uint32_t a1, uint32_t a2,
                                         uint32_t a3, uint32_t b0, uint32_t b1) {
    asm volatile(
        "mma.sync.aligned.m16n8k16.row.col.f32.bf16.bf16.f32 "
        "{%0,%1,%2,%3}, {%4,%5,%6,%7}, {%8,%9}, {%0,%1,%2,%3};"
        : "+f"(c[0]), "+f"(c[1]), "+f"(c[2]), "+f"(c[3])
        : "r"(a0), "r"(a1), "r"(a2), "r"(a3), "r"(b0), "r"(b1));
}
__device__ __forceinline__ uint32_t pk2(float a, float b) {
    __nv_bfloat162 t = __floats2bfloat162_rn(a, b);
    return *(uint32_t*)&t;
}

// ---------------- init ----------------
__global__ void k_zero_cnt(int total) {
    int i = blockIdx.x * blockDim.x + threadIdx.x;
    if (i < total) g_cnt[i] = 0;
}
__global__ void k_init_edges_count(const int* __restrict__ src, const int* __restrict__ dst) {
    int i = blockIdx.x * blockDim.x + threadIdx.x;
    if (i >= BATCH * NEDGE) return;
    int s = src[i], d = dst[i];
    g_edge[i] = make_int2(s, d);
    int b = i / NEDGE;
    atomicAdd(&g_cnt[b * NMAX + d], 1);
}

// ---------------- fused per-batch scan + CSR fill + s0 zero + sinfo build ----------------
// 3-phase scan: local prefix -> warp-scan of totals -> writeback. n_old==0 -> stage 1.
__global__ __launch_bounds__(1024) void k_scan_fill(int n, int n_old) {
    __shared__ int cur[NMAX];
    __shared__ int wpre[32];
    const int b = blockIdx.x, tid = threadIdx.x;
    const int lane = tid & 31, warp = tid >> 5;
    const int E = (n + 1023) >> 10;          // elems per thread (1 or 2)
    const int i0 = tid * E;

    // phase 1: local counts + running prefix
    int loc[2];
    int total = 0;
#pragma unroll
    for (int e = 0; e < 2; e++) {
        int v = 0;
        if (e < E && i0 + e < n) v = g_cnt[b * n + i0 + e];
        loc[e] = total;           // exclusive local prefix
        total += v;
    }
    // phase 2: block exclusive scan of per-thread totals
    int inc = total;
#pragma unroll
    for (int off = 1; off < 32; off <<= 1) {
        int u = __shfl_up_sync(0xffffffffu, inc, off);
        if (lane >= off) inc += u;
    }
    if (lane == 31) wpre[warp] = inc;
    __syncthreads();
    if (warp == 0) {
        int w = (lane < 32) ? wpre[lane] : 0;
        int wi = w;
#pragma unroll
        for (int off = 1; off < 32; off <<= 1) {
            int u = __shfl_up_sync(0xffffffffu, wi, off);
            if (lane >= off) wi += u;
        }
        wpre[lane] = wi - w;     // exclusive
    }
    __syncthreads();
    const int base = wpre[warp] + (inc - total);

    // phase 3: writeback rowstart/cur/s0/sinfo
#pragma unroll
    for (int e = 0; e < 2; e++) {
        if (e < E && i0 + e < n) {
            int i = i0 + e;
            int excl = base + loc[e];
            g_rowstart[b * n + i] = excl;
            cur[i] = excl;
            g_s0[b * n + i] = 0.0f;
            int ci = g_cnt[b * n + i];
            float c = rsqrtf((float)(ci + 1));
            int2 si;
            if (n_old) {
                int p = g_perm[b * n_old + i];
                int old = b * n_old + p;
                si.x = old;
                si.y = __float_as_int(g_tv[old] * c);
            } else {
                si.x = b * n + i;
                si.y = __float_as_int(c);
            }
            g_sinfo[b * n + i] = si;
        }
    }
    __syncthreads();
    // CSR fill: one LDG.64 per edge
#pragma unroll 4
    for (int e = tid; e < NEDGE; e += 1024) {
        int2 ed = g_edge[b * NEDGE + e];
        if (ed.y >= 0) {
            int pos = atomicAdd(&cur[ed.y], 1);
            g_csr[b * NEDGE + pos] = ed.x;
        }
    }
}

// ---------------- warp-per-row GCN aggregation + bf16 split ----------------
template<int VEC>
__global__ __launch_bounds__(256) void k_gather_w(const float* __restrict__ xin,
                                                  __nv_bfloat16* __restrict__ hi,
                                                  __nv_bfloat16* __restrict__ lo,
                                                  int n) {
    const int K = VEC * 128;
    const int gw = (blockIdx.x * 256 + threadIdx.x) >> 5;
    const int lane = threadIdx.x & 31;
    const int b = gw / n;
    const int bn = b * n;
    const int start = g_rowstart[gw];
    const int cnt = g_cnt[gw];
    const float dinv = rsqrtf((float)(cnt + 1));
    const int2 sself = g_sinfo[gw];

    float4 acc[VEC];
#pragma unroll
    for (int j = 0; j < VEC; j++) acc[j] = make_float4(0.f, 0.f, 0.f, 0.f);

    for (int base = 0; base < cnt; base += 32) {
        int m = min(32, cnt - base);
        int off = 0; float c = 0.0f;
        if (lane < m) {
            int s = g_csr[b * NEDGE + start + base + lane];
            int2 si = g_sinfo[bn + s];
            off = si.x * K;
            c = __int_as_float(si.y);
        }
#pragma unroll 8
        for (int e = 0; e < m; e++) {
            int o = __shfl_sync(0xffffffffu, off, e);
            float cc = __shfl_sync(0xffffffffu, c, e);
            const float4* p = (const float4*)(xin + o);
#pragma unroll
            for (int j = 0; j < VEC; j++) {
                float4 v = p[lane + j * 32];
                acc[j].x = fmaf(v.x, cc, acc[j].x);
                acc[j].y = fmaf(v.y, cc, acc[j].y);
                acc[j].z = fmaf(v.z, cc, acc[j].z);
                acc[j].w = fmaf(v.w, cc, acc[j].w);
            }
        }
    }
    const float scoef = __int_as_float(sself.y);
    const float4* selfp = (const float4*)(xin + (size_t)sself.x * K);
    uint2* hp = (uint2*)(hi + (size_t)gw * K);
    uint2* lp = (uint2*)(lo + (size_t)gw * K);
#pragma unroll
    for (int j = 0; j < VEC; j++) {
        float4 sv = selfp[lane + j * 32];
        float rx = dinv * fmaf(sv.x, scoef, acc[j].x);
        float ry = dinv * fmaf(sv.y, scoef, acc[j].y);
        float rz = dinv * fmaf(sv.z, scoef, acc[j].z);
        float rw = dinv * fmaf(sv.w, scoef, acc[j].w);
        float lx = rx - __bfloat162float(__float2bfloat16(rx));
        float ly = ry - __bfloat162float(__float2bfloat16(ry));
        float lz = rz - __bfloat162float(__float2bfloat16(rz));
        float lw = rw - __bfloat162float(__float2bfloat16(rw));
        hp[lane + j * 32] = make_uint2(pk2(rx, ry), pk2(rz, rw));
        lp[lane + j * 32] = make_uint2(pk2(lx, ly), pk2(lz, lw));
    }
}

// ---------------- weight split + transpose via smem tile ----------------
__global__ void k_split_w(const float* __restrict__ W, __nv_bfloat16* __restrict__ hi,
                          __nv_bfloat16* __restrict__ lo, int K) {
    __shared__ float tile[32][33];
    const int k0 = blockIdx.x * 32, n0 = blockIdx.y * 32;
    const int tx = threadIdx.x, ty = threadIdx.y;
#pragma unroll
    for (int j = 0; j < 4; j++) {
        int kr = ty + j * 8;
        tile[kr][tx] = W[(size_t)(k0 + kr) * 512 + n0 + tx];
    }
    __syncthreads();
#pragma unroll
    for (int j = 0; j < 4; j++) {
        int nr = ty + j * 8;
        float v = tile[tx][nr];
        __nv_bfloat16 h = __float2bfloat16(v);
        size_t o = (size_t)(n0 + nr) * K + k0 + tx;
        hi[o] = h;
        lo[o] = __float2bfloat16(v - __bfloat162float(h));
    }
}

// ---------------- split-bf16 tensor GEMM + fused bias/relu/scorer epilogue ----------------
// single __syncthreads per K-chunk: wait -> sync -> issue load(t+2) -> compute(t)
#define LDS_E   40
#define TILE_A  (128 * LDS_E * 2)
#define TILE_BS (256 * LDS_E * 2)
#define STAGE_B (2 * TILE_A + 2 * TILE_BS)
#define GEMM_SMEM (3 * STAGE_B)
__global__ __launch_bounds__(512, 1) void k_gemm_mma(
    const __nv_bfloat16* __restrict__ Ahi, const __nv_bfloat16* __restrict__ Alo,
    const __nv_bfloat16* __restrict__ Bhi, const __nv_bfloat16* __restrict__ Blo,
    float* __restrict__ C, const float* __restrict__ bias, const float* __restrict__ Wp,
    int M, int K)
{
    extern __shared__ __align__(128) char smem[];
    const uint32_t sb = smem_u32(smem);
    const int tid = threadIdx.x;
    const int wid = tid >> 5;
    const int lane = tid & 31;
    const int warp_m = wid & 3;
    const int warp_n = wid >> 2;
    const int rowBase = blockIdx.y * 128;
    const int colBase = blockIdx.x * 256;

    const int g = lane >> 3;
    const int a_m = lane & 15;
    const int a_k = (lane >> 4) << 3;
    const int b_n = lane - ((g == 0) ? 0 : (g == 3) ? 16 : 8);
    const int b_k = (g & 1) << 3;

    uint32_t aoff[2], boff[4];
#pragma unroll
    for (int mt = 0; mt < 2; mt++)
        aoff[mt] = ((warp_m * 32 + mt * 16 + a_m) * LDS_E + a_k) * 2;
#pragma unroll
    for (int ng = 0; ng < 4; ng++)
        boff[ng] = ((warp_n * 64 + ng * 16 + b_n) * LDS_E + b_k) * 2;

    float acc[2][8][4];
#pragma unroll
    for (int mt = 0; mt < 2; mt++)
#pragma unroll
        for (int nf = 0; nf < 8; nf++)
#pragma unroll
            for (int e = 0; e < 4; e++) acc[mt][nf][e] = 0.0f;

    const int nch = K >> 5;

    auto load_stage = [&](int t) {
        const uint32_t base = sb + (t % 3) * STAGE_B;
        const int kc0 = t << 5;
        {
            int r = tid >> 2, blk = tid & 3;
            uint32_t so = r * (LDS_E * 2) + blk * 16;
            size_t ga = (size_t)(rowBase + r) * K + kc0 + blk * 8;
            cp16(base + so,          Ahi + ga);
            cp16(base + TILE_A + so, Alo + ga);
        }
#pragma unroll
        for (int part = 0; part < 2; part++) {
            int idx = tid + part * 512;
            int r = idx >> 2, blk = idx & 3;
            uint32_t so = r * (LDS_E * 2) + blk * 16;
            size_t gb = (size_t)(colBase + r) * K + kc0 + blk * 8;
            cp16(base + 2 * TILE_A + so,           Bhi + gb);
            cp16(base + 2 * TILE_A + TILE_BS + so, Blo + gb);
        }
        asm volatile("cp.async.commit_group;" ::: "memory");
    };

    load_stage(0);
    if (nch > 1) load_stage(1);
    for (int t = 0; t < nch; t++) {
        if (t == nch - 1) {
            asm volatile("cp.async.wait_group 0;" ::: "memory");
        } else {
            asm volatile("cp.async.wait_group 1;" ::: "memory");
        }
        __syncthreads();   // also guards buffer (t-1)%3 reuse by load(t+2) below
        if (t + 2 < nch) load_stage(t + 2);

        const uint32_t base = sb + (t % 3) * STAGE_B;
        const uint32_t bbase = base + 2 * TILE_A;
#pragma unroll
        for (int kk = 0; kk < 2; kk++) {
            const uint32_t ko = kk * 32;
            uint32_t ah[2][4], al[2][4];
#pragma unroll
            for (int mt = 0; mt < 2; mt++) {
                ldsm4(ah[mt][0], ah[mt][1], ah[mt][2], ah[mt][3], base + aoff[mt] + ko);
                ldsm4(al[mt][0], al[mt][1], al[mt][2], al[mt][3], base + TILE_A + aoff[mt] + ko);
            }
#pragma unroll
            for (int half = 0; half < 2; half++) {
                uint32_t bh[4][2], bl[4][2];
#pragma unroll
                for (int gg = 0; gg < 2; gg++) {
                    int ng = half * 2 + gg;
                    uint32_t r0, r1, r2, r3;
                    ldsm4(r0, r1, r2, r3, bbase + boff[ng] + ko);
                    bh[gg * 2][0] = r0; bh[gg * 2][1] = r1;
                    bh[gg * 2 + 1][0] = r2; bh[gg * 2 + 1][1] = r3;
                    ldsm4(r0, r1, r2, r3, bbase + TILE_BS + boff[ng] + ko);
                    bl[gg * 2][0] = r0; bl[gg * 2][1] = r1;
                    bl[gg * 2 + 1][0] = r2; bl[gg * 2 + 1][1] = r3;
                }
#pragma unroll
                for (int mt = 0; mt < 2; mt++)
#pragma unroll
                    for (int q = 0; q < 4; q++) {
                        int nf = half * 4 + q;
                        mma_bf16(acc[mt][nf], ah[mt][0], ah[mt][1], ah[mt][2], ah[mt][3],
                                 bh[q][0], bh[q][1]);
                        mma_bf16(acc[mt][nf], ah[mt][0], ah[mt][1], ah[mt][2], ah[mt][3],
                                 bl[q][0], bl[q][1]);
                        mma_bf16(acc[mt][nf], al[mt][0], al[mt][1], al[mt][2], al[mt][3],
                                 bh[q][0], bh[q][1]);
                    }
            }
        }
    }

    float sdot[2][2] = {{0.f, 0.f}, {0.f, 0.f}};
#pragma unroll
    for (int mt = 0; mt < 2; mt++) {
        int r0 = rowBase + warp_m * 32 + mt * 16 + (lane >> 2);
        int r1 = r0 + 8;
#pragma unroll
        for (int nf = 0; nf < 8; nf++) {
            int col = colBase + warp_n * 64 + nf * 8 + (lane & 3) * 2;
            float b0 = bias[col], b1 = bias[col + 1];
            float w0 = Wp[col],   w1 = Wp[col + 1];
            float v00 = fmaxf(acc[mt][nf][0] + b0, 0.0f);
            float v01 = fmaxf(acc[mt][nf][1] + b1, 0.0f);
            float v10 = fmaxf(acc[mt][nf][2] + b0, 0.0f);
            float v11 = fmaxf(acc[mt][nf][3] + b1, 0.0f);
            *(float2*)(C + (size_t)r0 * 512 + col) = make_float2(v00, v01);
            *(float2*)(C + (size_t)r1 * 512 + col) = make_float2(v10, v11);
            sdot[mt][0] = fmaf(v00, w0, fmaf(v01, w1, sdot[mt][0]));
            sdot[mt][1] = fmaf(v10, w0, fmaf(v11, w1, sdot[mt][1]));
        }
    }
#pragma unroll
    for (int off = 1; off < 4; off <<= 1) {
#pragma unroll
        for (int mt = 0; mt < 2; mt++) {
            sdot[mt][0] += __shfl_xor_sync(0xffffffffu, sdot[mt][0], off);
            sdot[mt][1] += __shfl_xor_sync(0xffffffffu, sdot[mt][1], off);
        }
    }
    if ((lane & 3) == 0) {
#pragma unroll
        for (int mt = 0; mt < 2; mt++) {
            int r0 = rowBase + warp_m * 32 + mt * 16 + (lane >> 2);
            atomicAdd(&g_s0[r0], sdot[mt][0]);
            atomicAdd(&g_s0[r0 + 8], sdot[mt][1]);
        }
    }
}

// ---------------- score propagate (warp per row over CSR) ----------------
__global__ void k_score(const float* __restrict__ bp, int n) {
    int row = blockIdx.x * 8 + (threadIdx.x >> 5);
    if (row >= BATCH * n) return;
    int lane = threadIdx.x & 31;
    int b = row / n, bn = b * n;
    int start = g_rowstart[row];
    int cnt = g_cnt[row];
    float sum = 0.0f;
    for (int e = lane; e < cnt; e += 32) {
        int s = g_csr[b * NEDGE + start + e];
        sum += g_s0[bn + s] * rsqrtf((float)(g_cnt[bn + s] + 1));
    }
#pragma unroll
    for (int o = 16; o > 0; o >>= 1) sum += __shfl_down_sync(0xffffffffu, sum, o);
    if (lane == 0) {
        float deg = (float)(cnt + 1);
        g_score[row] = g_s0[row] / deg + rsqrtf(deg) * sum + bp[0];
    }
}

// ---------------- top-k: per-batch bitonic sort (+ tv store, next-stage cnt zero) ----------------
__global__ void k_topk(int n, int k, int kzero) {
    extern __shared__ char sm[];
    float* sv = (float*)sm;
    int* si = (int*)(sv + n);
    int b = blockIdx.x, tid = threadIdx.x;
    for (int i = tid; i < n; i += blockDim.x) { sv[i] = g_score[b * n + i]; si[i] = i; }
    __syncthreads();
    for (int ksz = 2; ksz <= n; ksz <<= 1) {
        for (int j = ksz >> 1; j > 0; j >>= 1) {
            for (int i = tid; i < n; i += blockDim.x) {
                int ixj = i ^ j;
                if (ixj > i) {
                    float v1 = sv[i], v2 = sv[ixj];
                    int i1 = si[i], i2 = si[ixj];
                    bool before = (v1 > v2) || (v1 == v2 && i1 < i2);
                    bool desc = ((i & ksz) == 0);
                    if (desc ? !before : before) {
                        sv[i] = v2; sv[ixj] = v1; si[i] = i2; si[ixj] = i1;
                    }
                }
            }
            __syncthreads();
        }
    }
    for (int i = tid; i < n; i += blockDim.x) g_newidx[b * n + i] = -1;
    __syncthreads();
    for (int t = tid; t < k; t += blockDim.x) {
        int p = si[t];
        g_perm[b * n + t] = p;
        g_newidx[b * n + p] = t;
        g_tv[b * n + p] = tanhf(sv[t]);
    }
    if (kzero)
        for (int j = tid; j < kzero; j += blockDim.x) g_cnt[b * kzero + j] = 0;
}

// ---------------- readout (max/mean over selected rows) ----------------
__global__ __launch_bounds__(128) void k_pool_readout(const float* __restrict__ h,
                                                      int n, int k, int first) {
    __shared__ float tv[1024];
    __shared__ int   pp[1024];
    const int b = blockIdx.x, fc = blockIdx.y, t = threadIdx.x;
    for (int r = t; r < k; r += 128) {
        int p = g_perm[b * n + r];
        pp[r] = p;
        tv[r] = g_tv[b * n + p];
    }
    __syncthreads();
    const int f = fc * 128 + t;
    float mx = -INFINITY, sm = 0.0f;
    for (int r = 0; r < k; r++) {
        float v = h[((size_t)b * n + pp[r]) * NHID + f] * tv[r];
        mx = fmaxf(mx, v);
        sm += v;
    }
    if (first) {
        g_z[b * 1024 + f] = mx;
        g_z[b * 1024 + 512 + f] = sm / (float)k;
    } else {
        g_z[b * 1024 + f] += mx;
        g_z[b * 1024 + 512 + f] += sm / (float)k;
    }
}

// ---------------- edge relabel + count for next stage ----------------
__global__ void k_edge_update_count(int n, int k) {
    int i = blockIdx.x * blockDim.x + threadIdx.x;
    if (i >= BATCH * NEDGE) return;
    int b = i / NEDGE;
    int2 e = g_edge[i];
    if (e.y >= 0) {
        int ns = g_newidx[b * n + e.x];
        int nd = g_newidx[b * n + e.y];
        if (ns >= 0 && nd >= 0) {
            g_edge[i] = make_int2(ns, nd);
            atomicAdd(&g_cnt[b * k + nd], 1);
        } else {
            g_edge[i] = make_int2(0, -1);
        }
    }
}

// ---------------- head ----------------
__global__ void k_head(const float* __restrict__ l1W, const float* __restrict__ l1b,
                       const float* __restrict__ l2W, const float* __restrict__ l2b,
                       const float* __restrict__ piW, const float* __restrict__ pib,
                       const float* __restrict__ vW, const float* __restrict__ vb,
                       float* __restrict__ out) {
    __shared__ float zz[1024];
    __shared__ float z1[512];
    __shared__ float z2[256];
    __shared__ float lg[128];
    __shared__ float stats[2];
    int b = blockIdx.x, tid = threadIdx.x;
    for (int i = tid; i < 1024; i += 256) zz[i] = g_z[b * 1024 + i];
    __syncthreads();
    for (int j = tid; j < 512; j += 256) {
        float a = l1b[j];
        for (int i = 0; i < 1024; i++) a = fmaf(zz[i], l1W[i * 512 + j], a);
        z1[j] = fmaxf(a, 0.0f);
    }
    __syncthreads();
    {
        int j = tid;
        float a = l2b[j];
        for (int i = 0; i < 512; i++) a = fmaf(z1[i], l2W[i * 256 + j], a);
        z2[j] = fmaxf(a, 0.0f);
    }
    __syncthreads();
    if (tid < 128) {
        float a = pib[tid];
        for (int i = 0; i < 256; i++) a = fmaf(z2[i], piW[i * 128 + tid], a);
        lg[tid] = a;
    } else if (tid == 128) {
        float a = vb[0];
        for (int i = 0; i < 256; i++) a = fmaf(z2[i], vW[i], a);
        out[BATCH * RULES + b] = fmaxf(a, 0.0f);
    }
    __syncthreads();
    if (tid == 0) {
        float mx = -INFINITY;
        for (int i = 0; i < 128; i++) mx = fmaxf(mx, lg[i]);
        float s = 0.0f;
        for (int i = 0; i < 128; i++) s += expf(lg[i] - mx);
        stats[0] = mx;
        stats[1] = logf(s);
    }
    __syncthreads();
    if (tid < 128) out[b * RULES + tid] = lg[tid] - stats[0] - stats[1];
}

// ---------------- host orchestration ----------------
extern "C" void kernel_launch(void* const* d_in, const int* in_sizes, int n_in,
                              void* d_out, int out_size) {
    const float* x    = (const float*)d_in[0];
    const int*   src  = (const int*)d_in[1];
    const int*   dst  = (const int*)d_in[2];
    const float* W1   = (const float*)d_in[3];
    const float* b1   = (const float*)d_in[4];
    const float* Wp1  = (const float*)d_in[5];
    const float* bp1  = (const float*)d_in[6];
    const float* W2   = (const float*)d_in[7];
    const float* b2   = (const float*)d_in[8];
    const float* Wp2  = (const float*)d_in[9];
    const float* bp2  = (const float*)d_in[10];
    const float* W3   = (const float*)d_in[11];
    const float* b3   = (const float*)d_in[12];
    const float* Wp3  = (const float*)d_in[13];
    const float* bp3  = (const float*)d_in[14];
    const float* l1W  = (const float*)d_in[15];
    const float* l1b  = (const float*)d_in[16];
    const float* l2W  = (const float*)d_in[17];
    const float* l2b  = (const float*)d_in[18];
    const float* piW  = (const float*)d_in[19];
    const float* pib  = (const float*)d_in[20];
    const float* vW   = (const float*)d_in[21];
    const float* vb   = (const float*)d_in[22];
    float* out = (float*)d_out;

    float *pA = nullptr, *pB = nullptr;
    __nv_bfloat16 *ahi = nullptr, *alo = nullptr;
    __nv_bfloat16 (*whi)[NHID * NHID] = nullptr, (*wlo)[NHID * NHID] = nullptr;
    cudaGetSymbolAddress((void**)&pA, g_bufA);
    cudaGetSymbolAddress((void**)&pB, g_bufB);
    cudaGetSymbolAddress((void**)&ahi, g_ahi);
    cudaGetSymbolAddress((void**)&alo, g_alo);
    cudaGetSymbolAddress((void**)&whi, g_whi);
    cudaGetSymbolAddress((void**)&wlo, g_wlo);

    cudaFuncSetAttribute(k_gemm_mma, cudaFuncAttributeMaxDynamicSharedMemorySize, GEMM_SMEM);

    const int EB = BATCH * NEDGE;

    // launch order keeps capture slot #4 = stage-1 k_scan_fill (verify the new scan)
    k_zero_cnt<<<(BATCH * NMAX + 255) / 256, 256>>>(BATCH * NMAX);            // 1
    k_init_edges_count<<<(EB + 255) / 256, 256>>>(src, dst);                  // 2
    k_split_w<<<dim3(FIN / 32, 16),  dim3(32, 8)>>>(W1, whi[0], wlo[0], FIN); // 3
    // ---- stage 1: n=2048, K=256 ----
    k_scan_fill<<<BATCH, 1024>>>(2048, 0);                                    // 4 (captured)
    k_gather_w<2><<<BATCH * 2048 / 8, 256>>>(x, ahi, alo, 2048);
    k_gemm_mma<<<dim3(2, BATCH * 2048 / 128), 512, GEMM_SMEM>>>(
        ahi, alo, whi[0], wlo[0], pA, b1, Wp1, BATCH * 2048, FIN);
    k_split_w<<<dim3(NHID / 32, 16), dim3(32, 8)>>>(W2, whi[1], wlo[1], NHID);
    k_split_w<<<dim3(NHID / 32, 16), dim3(32, 8)>>>(W3, whi[2], wlo[2], NHID);
    k_score<<<BATCH * 2048 / 8, 256>>>(bp1, 2048);
    k_topk<<<BATCH, 1024, 2048 * 8>>>(2048, 1024, 1024);
    k_pool_readout<<<dim3(BATCH, 4), 128>>>(pA, 2048, 1024, 1);
    k_edge_update_count<<<(EB + 255) / 256, 256>>>(2048, 1024);

    // ---- stage 2: n=1024, K=512 ----
    k_scan_fill<<<BATCH, 1024>>>(1024, 2048);
    k_gather_w<4><<<BATCH * 1024 / 8, 256>>>(pA, ahi, alo, 1024);
    k_gemm_mma<<<dim3(2, BATCH * 1024 / 128), 512, GEMM_SMEM>>>(
        ahi, alo, whi[1], wlo[1], pB, b2, Wp2, BATCH * 1024, NHID);
    k_score<<<BATCH * 1024 / 8, 256>>>(bp2, 1024);
    k_topk<<<BATCH, 1024, 1024 * 8>>>(1024, 512, 512);
    k_pool_readout<<<dim3(BATCH, 4), 128>>>(pB, 1024, 512, 0);
    k_edge_update_count<<<(EB + 255) / 256, 256>>>(1024, 512);

    // ---- stage 3: n=512, K=512 ----
    k_scan_fill<<<BATCH, 1024>>>(512, 1024);
    k_gather_w<4><<<BATCH * 512 / 8, 256>>>(pB, ahi, alo, 512);
    k_gemm_mma<<<dim3(2, BATCH * 512 / 128), 512, GEMM_SMEM>>>(
        ahi, alo, whi[2], wlo[2], pA, b3, Wp3, BATCH * 512, NHID);
    k_score<<<BATCH * 512 / 8, 256>>>(bp3, 512);
    k_topk<<<BATCH, 1024, 512 * 8>>>(512, 256, 0);
    k_pool_readout<<<dim3(BATCH, 4), 128>>>(pA, 512, 256, 0);

    k_head<<<BATCH, 256>>>(l1W, l1b, l2W, l2b, piW, pib, vW, vb, out);
}